// round 13
// baseline (speedup 1.0000x reference)
#include <cuda_runtime.h>
#include <cuda_bf16.h>
#include <cuda_fp16.h>
#include <cstdint>

#define NP 200000
#define NA 100000
#define EE 1000000
#define HH 32

#define GEMM_BLKS_P 1563          // (NP+127)/128
#define GEMM_BLKS_A 782           // (NA+127)/128
#define GEMM_BLKS   (GEMM_BLKS_P + GEMM_BLKS_A)
#define HIST_BLKS   11719         // (3*EE+255)/256
#define PA_BLKS_P 25000           // NP/8
#define PA_BLKS_A 12500           // NA/8

// ---------------- device scratch ----------------
// g_deg and g_cnt are ZERO at kernel_launch entry: zero-initialized at module
// load, and re-zeroed by k_out at the end of every run (state-restoring graph).
__device__ int g_deg[2 * NP + NA];
__device__ int g_cur[2 * NP + NA];
__device__ int g_rp [2 * NP + NA];
__device__ int g_cnt[3];
__device__ int g_col[3 * EE];

// plane-split projected features; gathered planes fp16, self-read planes fp32
__device__ __align__(16) __half g_P0[(size_t)NP * 32];  // x@W1l_c        (gathered)
__device__ __align__(16) __half g_P1[(size_t)NP * 32];  // x@W1l_rev      (gathered)
__device__ __align__(16) float  g_P2[(size_t)NP * 32];  // x@(W1r_c+W1r_w)(self)
__device__ __align__(16) __half g_A0[(size_t)NA * 32];  // x@W1l_w        (gathered)
__device__ __align__(16) float  g_A1[(size_t)NA * 32];  // x@W1r_rev      (self)
__device__ float g_zc[NP], g_zr[NP], g_zw[NA];

// bf16 split B images, row-major [N][2K]: cols 0..K-1 = hi(W), K..2K-1 = lo(W)
__device__ __align__(16) __nv_bfloat16 g_WbP[96 * 256];
__device__ __align__(16) __nv_bfloat16 g_WbA[64 * 128];
__device__ float g_b1[HH], g_brev[HH], g_uc[HH], g_uw[HH], g_wr2[HH];
__device__ float g_cbias;

// ---------------- helpers ----------------
__device__ __forceinline__ uint32_t smem_u32(const void* p) {
    uint32_t a;
    asm("{ .reg .u64 t; cvta.to.shared.u64 t, %1; cvt.u32.u64 %0, t; }" : "=r"(a) : "l"(p));
    return a;
}
__device__ __forceinline__ unsigned int pack_bf16(float a, float b) {
    __nv_bfloat162 h = __floats2bfloat162_rn(a, b);
    return *reinterpret_cast<unsigned int*>(&h);
}
__device__ __forceinline__ void ldsm4(uint32_t& r0, uint32_t& r1, uint32_t& r2, uint32_t& r3,
                                      uint32_t addr) {
    asm volatile("ldmatrix.sync.aligned.m8n8.x4.shared.b16 {%0,%1,%2,%3}, [%4];"
                 : "=r"(r0), "=r"(r1), "=r"(r2), "=r"(r3) : "r"(addr));
}
__device__ __forceinline__ void mma16816(float* d, const uint32_t* a, uint32_t b0, uint32_t b1) {
    asm volatile(
        "mma.sync.aligned.m16n8k16.row.col.f32.bf16.bf16.f32 "
        "{%0,%1,%2,%3}, {%4,%5,%6,%7}, {%8,%9}, {%0,%1,%2,%3};"
        : "+f"(d[0]), "+f"(d[1]), "+f"(d[2]), "+f"(d[3])
        : "r"(a[0]), "r"(a[1]), "r"(a[2]), "r"(a[3]), "r"(b0), "r"(b1));
}

// ---------------- weight prep (stream 0) ----------------
__global__ void k_prep(const float* __restrict__ W1l_c,  const float* __restrict__ b1l_c,
                       const float* __restrict__ W1r_c,  const float* __restrict__ W1l_w,
                       const float* __restrict__ b1l_w,  const float* __restrict__ W1r_w,
                       const float* __restrict__ W1l_rev,const float* __restrict__ b1l_rev,
                       const float* __restrict__ W1r_rev,const float* __restrict__ W2l_c,
                       const float* __restrict__ b2l_c,  const float* __restrict__ W2r_c,
                       const float* __restrict__ W2l_w,  const float* __restrict__ b2l_w,
                       const float* __restrict__ W2r_w,  const float* __restrict__ Wh,
                       const float* __restrict__ bh) {
    int idx = blockIdx.x * 256 + threadIdx.x;
    const int stride = 48 * 256;

    for (int q = idx; q < 96 * 256; q += stride) {
        int n = q >> 8, kc = q & 255;
        int k = kc & 127;
        bool lo = kc >= 128;
        float v;
        if (n < 32)      v = W1l_c[k * HH + n];
        else if (n < 64) v = W1l_rev[k * HH + n - 32];
        else             v = W1r_c[k * HH + n - 64] + W1r_w[k * HH + n - 64];
        __nv_bfloat16 h = __float2bfloat16(v);
        g_WbP[q] = lo ? __float2bfloat16(v - __bfloat162float(h)) : h;
    }
    for (int q = idx; q < 64 * 128; q += stride) {
        int n = q >> 7, kc = q & 127;
        int k = kc & 63;
        bool lo = kc >= 64;
        float v = (n < 32) ? W1l_w[k * HH + n] : W1r_rev[k * HH + n - 32];
        __nv_bfloat16 h = __float2bfloat16(v);
        g_WbA[q] = lo ? __float2bfloat16(v - __bfloat162float(h)) : h;
    }
    if (idx < HH) {
        g_b1[idx]   = b1l_c[idx] + b1l_w[idx];
        g_brev[idx] = b1l_rev[idx];
        float uc = 0.f, uw = 0.f, wr = 0.f;
        for (int j = 0; j < HH; ++j) {
            float wh = Wh[j];
            uc += W2l_c[idx * HH + j] * wh;
            uw += W2l_w[idx * HH + j] * wh;
            wr += (W2r_c[idx * HH + j] + W2r_w[idx * HH + j]) * wh;
        }
        g_uc[idx] = uc; g_uw[idx] = uw; g_wr2[idx] = wr;
    }
    if (idx == 0) {
        float cb = bh[0];
        for (int j = 0; j < HH; ++j) cb += (b2l_c[j] + b2l_w[j]) * Wh[j];
        g_cbias = cb;
    }
}

// ---------------- CSR build (side stream) ----------------
__global__ void k_hist3(const int* __restrict__ dc, const int* __restrict__ dw,
                        const int* __restrict__ dr) {
    int e = blockIdx.x * blockDim.x + threadIdx.x;
    if (e < EE)            atomicAdd(&g_deg[__ldg(dc + e)], 1);
    else if (e < 2 * EE)   atomicAdd(&g_deg[NP + __ldg(dw + e - EE)], 1);
    else if (e < 3 * EE)   atomicAdd(&g_deg[2 * NP + __ldg(dr + e - 2 * EE)], 1);
}

__global__ void k_alloc3() {
    __shared__ int sm[256];
    __shared__ int sbase;
    int b = blockIdx.x;
    int off, n, cidx, lb;
    if (b < 196)      { off = 0;      n = NP; cidx = 0; lb = b; }
    else if (b < 392) { off = NP;     n = NP; cidx = 1; lb = b - 196; }
    else              { off = 2 * NP; n = NA; cidx = 2; lb = b - 392; }

    int t = threadIdx.x;
    int idx0 = lb * 1024 + t * 4;
    int d0 = (idx0 + 0 < n) ? g_deg[off + idx0 + 0] : 0;
    int d1 = (idx0 + 1 < n) ? g_deg[off + idx0 + 1] : 0;
    int d2 = (idx0 + 2 < n) ? g_deg[off + idx0 + 2] : 0;
    int d3 = (idx0 + 3 < n) ? g_deg[off + idx0 + 3] : 0;
    int s = d0 + d1 + d2 + d3;
    sm[t] = s;
    __syncthreads();
    for (int o = 1; o < 256; o <<= 1) {
        int v = (t >= o) ? sm[t - o] : 0;
        __syncthreads();
        sm[t] += v;
        __syncthreads();
    }
    if (t == 255) sbase = atomicAdd(&g_cnt[cidx], sm[255]);
    __syncthreads();
    int start = sbase + sm[t] - s;
    if (idx0 + 0 < n) { g_rp[off + idx0 + 0] = start; g_cur[off + idx0 + 0] = start; start += d0; }
    if (idx0 + 1 < n) { g_rp[off + idx0 + 1] = start; g_cur[off + idx0 + 1] = start; start += d1; }
    if (idx0 + 2 < n) { g_rp[off + idx0 + 2] = start; g_cur[off + idx0 + 2] = start; start += d2; }
    if (idx0 + 3 < n) { g_rp[off + idx0 + 3] = start; g_cur[off + idx0 + 3] = start; }
}

__global__ void k_fill3(const int* __restrict__ sc, const int* __restrict__ dc,
                        const int* __restrict__ sw, const int* __restrict__ dw,
                        const int* __restrict__ sr, const int* __restrict__ dr) {
    int e = blockIdx.x * blockDim.x + threadIdx.x;
    const int* s; const int* d; int off, colOff, le;
    if (e < EE)          { s = sc; d = dc; off = 0;      colOff = 0;      le = e; }
    else if (e < 2 * EE) { s = sw; d = dw; off = NP;     colOff = EE;     le = e - EE; }
    else if (e < 3 * EE) { s = sr; d = dr; off = 2 * NP; colOff = 2 * EE; le = e - 2 * EE; }
    else return;
    int dd = __ldg(d + le);
    int p = atomicAdd(&g_cur[off + dd], 1);
    g_col[colOff + p] = __ldg(s + le);
}

// ---------------- bf16 3-term-split GEMM body ----------------
template <int K, int N, int WHICH>
__device__ __forceinline__ void gemm_body(const float* __restrict__ A,
                                          const __nv_bfloat16* __restrict__ B, // [N][2K]
                                          int M, int row0,
                                          __nv_bfloat16* As, __nv_bfloat16* Bs) {
    constexpr int CK  = 32;
    constexpr int NCH = K / CK;
    constexpr int STR = 2 * CK + 8;   // 72
    constexpr int NP2 = N / 32;
    constexpr int NT  = N / 16;

    const int tid = threadIdx.x;
    const int warp = tid >> 5, lane = tid & 31;
    const int wr = warp & 3, wc = warp >> 2;
    const int lr = lane & 7, sel = lane >> 3;
    const uint32_t As_u = smem_u32(As), Bs_u = smem_u32(Bs);

    float d[2][NT][4];
#pragma unroll
    for (int rg = 0; rg < 2; ++rg)
#pragma unroll
        for (int nt = 0; nt < NT; ++nt)
#pragma unroll
            for (int j = 0; j < 4; ++j) d[rg][nt][j] = 0.f;

#pragma unroll
    for (int ch = 0; ch < NCH; ++ch) {
        __syncthreads();
        // A chunk: 128 rows x 32 f32, split hi/lo
        {
            const int q = tid & 3, r0 = tid >> 2;
#pragma unroll
            for (int i = 0; i < 2; ++i) {
                int r = r0 + 64 * i;
                int gr = row0 + r; if (gr > M - 1) gr = M - 1;
                const float4* p = (const float4*)(A + (size_t)gr * K + ch * CK + q * 8);
                float4 va = p[0], vb = p[1];
                float f[8] = {va.x, va.y, va.z, va.w, vb.x, vb.y, vb.z, vb.w};
                float h[8], l[8];
#pragma unroll
                for (int j = 0; j < 8; ++j) {
                    h[j] = __bfloat162float(__float2bfloat16(f[j]));
                    l[j] = f[j] - h[j];
                }
                uint4 HI = {pack_bf16(h[0], h[1]), pack_bf16(h[2], h[3]),
                            pack_bf16(h[4], h[5]), pack_bf16(h[6], h[7])};
                uint4 LO = {pack_bf16(l[0], l[1]), pack_bf16(l[2], l[3]),
                            pack_bf16(l[4], l[5]), pack_bf16(l[6], l[7])};
                *(uint4*)(As + r * STR + q * 8)      = HI;
                *(uint4*)(As + r * STR + CK + q * 8) = LO;
            }
        }
        // B chunk: grp 0-3 = hi cols, 4-7 = lo cols
        for (int u = tid; u < N * 8; u += 256) {
            int n = u >> 3, grp = u & 7;
            int srcCol = (grp < 4) ? (ch * CK + grp * 8) : (K + ch * CK + (grp - 4) * 8);
            *(uint4*)(Bs + n * STR + grp * 8) = *(const uint4*)(B + n * 2 * K + srcCol);
        }
        __syncthreads();

#pragma unroll
        for (int ks = 0; ks < CK / 16; ++ks) {
            const uint32_t a_base = As_u + (uint32_t)(((wr * 32 + lr + (sel & 1) * 8) * STR +
                                                       ks * 16 + (sel >> 1) * 8) * 2);
            const uint32_t b_base = Bs_u + (uint32_t)(((wc * (N / 2) + lr + (sel >> 1) * 8) * STR +
                                                       ks * 16 + (sel & 1) * 8) * 2);
            uint32_t ah[2][4], al[2][4];
#pragma unroll
            for (int rg = 0; rg < 2; ++rg)
                ldsm4(ah[rg][0], ah[rg][1], ah[rg][2], ah[rg][3],
                      a_base + (uint32_t)(rg * 16 * STR * 2));
#pragma unroll
            for (int rg = 0; rg < 2; ++rg)
                ldsm4(al[rg][0], al[rg][1], al[rg][2], al[rg][3],
                      a_base + (uint32_t)((rg * 16 * STR + CK) * 2));
#pragma unroll
            for (int np = 0; np < NP2; ++np) {
                uint32_t b0, b1, b2, b3;
                ldsm4(b0, b1, b2, b3, b_base + (uint32_t)(np * 16 * STR * 2));
#pragma unroll
                for (int rg = 0; rg < 2; ++rg) {
                    mma16816(d[rg][2 * np],     ah[rg], b0, b1);
                    mma16816(d[rg][2 * np + 1], ah[rg], b2, b3);
                }
#pragma unroll
                for (int rg = 0; rg < 2; ++rg) {
                    mma16816(d[rg][2 * np],     al[rg], b0, b1);
                    mma16816(d[rg][2 * np + 1], al[rg], b2, b3);
                }
                ldsm4(b0, b1, b2, b3, b_base + (uint32_t)((np * 16 * STR + CK) * 2));
#pragma unroll
                for (int rg = 0; rg < 2; ++rg) {
                    mma16816(d[rg][2 * np],     ah[rg], b0, b1);
                    mma16816(d[rg][2 * np + 1], ah[rg], b2, b3);
                }
            }
        }
    }

    // epilogue -> plane-split outputs (gathered planes fp16, self planes fp32)
    const int g = lane >> 2, t = lane & 3;
#pragma unroll
    for (int rg = 0; rg < 2; ++rg) {
        const int r1 = row0 + wr * 32 + rg * 16 + g, r2 = r1 + 8;
#pragma unroll
        for (int nt = 0; nt < NT; ++nt) {
            int col = wc * (N / 2) + nt * 8 + 2 * t;
            int pl = col >> 5, cc = col & 31;
            bool fp16plane; __half* H; float* F;
            if (WHICH == 0) {
                fp16plane = (pl < 2);
                H = (pl == 0) ? g_P0 : g_P1;
                F = g_P2;
            } else {
                fp16plane = (pl == 0);
                H = g_A0;
                F = g_A1;
            }
            if (fp16plane) {
                __half2 v1 = __floats2half2_rn(d[rg][nt][0], d[rg][nt][1]);
                __half2 v2 = __floats2half2_rn(d[rg][nt][2], d[rg][nt][3]);
                if (r1 < M) *(__half2*)(H + (size_t)r1 * 32 + cc) = v1;
                if (r2 < M) *(__half2*)(H + (size_t)r2 * 32 + cc) = v2;
            } else {
                if (r1 < M) *(float2*)(F + (size_t)r1 * 32 + cc) = make_float2(d[rg][nt][0], d[rg][nt][1]);
                if (r2 < M) *(float2*)(F + (size_t)r2 * 32 + cc) = make_float2(d[rg][nt][2], d[rg][nt][3]);
            }
        }
    }
}

__global__ void __launch_bounds__(256, 2) k_gemm_all(const float* __restrict__ xp,
                                                     const float* __restrict__ xa) {
    __shared__ __nv_bfloat16 sm[128 * 72 + 96 * 72];
    if (blockIdx.x < GEMM_BLKS_P)
        gemm_body<128, 96, 0>(xp, g_WbP, NP, blockIdx.x * 128, sm, sm + 128 * 72);
    else
        gemm_body<64, 64, 1>(xa, g_WbA, NA, (blockIdx.x - GEMM_BLKS_P) * 128, sm, sm + 128 * 72);
}

// ---------------- layer-1 gathers + layer-2 scalar projections (fp16 gathers, MLP=8) ----------------
__device__ __forceinline__ float gather_mean16(const int* __restrict__ col, int d,
                                               const __half* __restrict__ base, int lane) {
    float acc = 0.f;
    for (int e = 0; e < d; e += 8) {
        int idx[8];
        float v[8];
#pragma unroll
        for (int j = 0; j < 8; ++j) idx[j] = (e + j < d) ? __ldg(col + e + j) : -1;
#pragma unroll
        for (int j = 0; j < 8; ++j)
            v[j] = (idx[j] >= 0) ? __half2float(__ldg(base + ((size_t)idx[j] << 5) + lane)) : 0.f;
        acc += ((v[0] + v[1]) + (v[2] + v[3])) + ((v[4] + v[5]) + (v[6] + v[7]));
    }
    return acc / fmaxf((float)d, 1.f);
}

__global__ void __launch_bounds__(256) k_pa() {
    int lane = threadIdx.x & 31;
    if (blockIdx.x < PA_BLKS_P) {
        int w = blockIdx.x * 8 + (threadIdx.x >> 5);
        int s  = __ldg(&g_rp[w]);      int d  = __ldg(&g_deg[w]);
        int s2 = __ldg(&g_rp[NP + w]); int d2 = __ldg(&g_deg[NP + w]);

        float mc = gather_mean16(g_col + s, d, g_P0, lane);
        float mw = gather_mean16(g_col + EE + s2, d2, g_A0, lane);

        float p = mc + mw + __ldg(g_P2 + ((size_t)w << 5) + lane) + g_b1[lane];
        p = fmaxf(p, 0.f);
        float zc = p * g_uc[lane];
        float zr = p * g_wr2[lane];
#pragma unroll
        for (int o = 16; o; o >>= 1) {
            zc += __shfl_xor_sync(0xFFFFFFFFu, zc, o);
            zr += __shfl_xor_sync(0xFFFFFFFFu, zr, o);
        }
        if (lane == 0) { g_zc[w] = zc; g_zr[w] = zr; }
    } else {
        int w = (blockIdx.x - PA_BLKS_P) * 8 + (threadIdx.x >> 5);
        int s = __ldg(&g_rp[2 * NP + w]); int d = __ldg(&g_deg[2 * NP + w]);
        float mr = gather_mean16(g_col + 2 * EE + s, d, g_P1, lane);

        float a1 = mr + __ldg(g_A1 + ((size_t)w << 5) + lane) + g_brev[lane];
        a1 = fmaxf(a1, 0.f);
        float zw = a1 * g_uw[lane];
#pragma unroll
        for (int o = 16; o; o >>= 1) zw += __shfl_xor_sync(0xFFFFFFFFu, zw, o);
        if (lane == 0) g_zw[w] = zw;
    }
}

// ---------------- layer 2 scalar aggregation + head; restores g_deg/g_cnt to zero ----------------
__device__ __forceinline__ float gather_mean1(const int* __restrict__ col, int d,
                                              const float* __restrict__ z) {
    float acc = 0.f;
    for (int e = 0; e < d; e += 8) {
        int idx[8];
        float v[8];
#pragma unroll
        for (int j = 0; j < 8; ++j) idx[j] = (e + j < d) ? __ldg(col + e + j) : -1;
#pragma unroll
        for (int j = 0; j < 8; ++j) v[j] = (idx[j] >= 0) ? __ldg(z + idx[j]) : 0.f;
        acc += ((v[0] + v[1]) + (v[2] + v[3])) + ((v[4] + v[5]) + (v[6] + v[7]));
    }
    return acc / fmaxf((float)d, 1.f);
}

__global__ void __launch_bounds__(256) k_out(float* __restrict__ out) {
    int i = blockIdx.x * blockDim.x + threadIdx.x;
    if (i >= NP) return;
    int s  = __ldg(&g_rp[i]);      int d  = __ldg(&g_deg[i]);
    int s2 = __ldg(&g_rp[NP + i]); int d2 = __ldg(&g_deg[NP + i]);
    float sc = gather_mean1(g_col + s, d, g_zc);
    float sw = gather_mean1(g_col + EE + s2, d2, g_zw);
    out[i] = sc + sw + __ldg(&g_zr[i]) + g_cbias;
    // state restore for next graph replay
    g_deg[i] = 0;
    g_deg[NP + i] = 0;
    if (i < NA) g_deg[2 * NP + i] = 0;
    if (i < 3) g_cnt[i] = 0;
}

// ---------------- launch: fork/join two-branch schedule ----------------
extern "C" void kernel_launch(void* const* d_in, const int* in_sizes, int n_in,
                              void* d_out, int out_size) {
    const float* x_paper  = (const float*)d_in[0];
    const float* x_author = (const float*)d_in[1];
    const int*   ei_c     = (const int*)d_in[2];
    const int*   ei_w     = (const int*)d_in[3];
    const int*   ei_r     = (const int*)d_in[4];
    float* out = (float*)d_out;

    static cudaStream_t s_side = nullptr;
    static cudaEvent_t s_evF = nullptr, s_evJ = nullptr;
    if (s_side == nullptr) {
        cudaStreamCreateWithFlags(&s_side, cudaStreamNonBlocking);
        cudaEventCreateWithFlags(&s_evF, cudaEventDisableTiming);
        cudaEventCreateWithFlags(&s_evJ, cudaEventDisableTiming);
    }

    // fork side branch from root of stream 0
    cudaEventRecord(s_evF, 0);
    cudaStreamWaitEvent(s_side, s_evF, 0);

    // side branch: CSR build (lean kernels; co-resident with GEMM)
    k_hist3<<<HIST_BLKS, 256, 0, s_side>>>(ei_c + EE, ei_w + EE, ei_r + EE);
    k_alloc3<<<490, 256, 0, s_side>>>();
    k_fill3<<<HIST_BLKS, 256, 0, s_side>>>(ei_c, ei_c + EE, ei_w, ei_w + EE, ei_r, ei_r + EE);
    cudaEventRecord(s_evJ, s_side);

    // main branch: weight prep + projection GEMM
    k_prep<<<48, 256>>>(
        (const float*)d_in[5],  (const float*)d_in[6],  (const float*)d_in[7],
        (const float*)d_in[8],  (const float*)d_in[9],  (const float*)d_in[10],
        (const float*)d_in[11], (const float*)d_in[12], (const float*)d_in[13],
        (const float*)d_in[14], (const float*)d_in[15], (const float*)d_in[16],
        (const float*)d_in[17], (const float*)d_in[18], (const float*)d_in[19],
        (const float*)d_in[23], (const float*)d_in[24]);
    k_gemm_all<<<GEMM_BLKS, 256>>>(x_paper, x_author);

    // join: gathers need both branches
    cudaStreamWaitEvent(0, s_evJ, 0);
    k_pa<<<PA_BLKS_P + PA_BLKS_A, 256>>>();
    k_out<<<(NP + 255) / 256, 256>>>(out);
}

// round 14
// speedup vs baseline: 1.0261x; 1.0261x over previous
#include <cuda_runtime.h>
#include <cuda_bf16.h>
#include <cuda_fp16.h>
#include <cstdint>

#define NP 200000
#define NA 100000
#define EE 1000000
#define HH 32

#define GEMM_BLKS_P 1563          // (NP+127)/128
#define GEMM_BLKS_A 782           // (NA+127)/128
#define GEMM_BLKS   (GEMM_BLKS_P + GEMM_BLKS_A)
#define HIST_BLKS   11719         // (3*EE+255)/256
#define PA_BLKS_P 25000           // NP/8
#define PA_BLKS_A 12500           // NA/8

// ---------------- device scratch ----------------
// g_deg / g_cnt are ZERO at entry: zero-init at load, re-zeroed by k_out each run.
__device__ int g_deg[2 * NP + NA];
__device__ int g_cur[2 * NP + NA];
__device__ int g_rp [2 * NP + NA];
__device__ int g_cnt[3];
__device__ int g_col[3 * EE];

// plane-split projected features; gathered planes fp16, self-read planes fp32
__device__ __align__(16) __half g_P0[(size_t)NP * 32];  // x@W1l_c        (gathered)
__device__ __align__(16) __half g_P1[(size_t)NP * 32];  // x@W1l_rev      (gathered)
__device__ __align__(16) float  g_P2[(size_t)NP * 32];  // x@(W1r_c+W1r_w)(self)
__device__ __align__(16) __half g_A0[(size_t)NA * 32];  // x@W1l_w        (gathered)
__device__ __align__(16) float  g_A1[(size_t)NA * 32];  // x@W1r_rev      (self)
__device__ float g_zc[NP], g_zr[NP], g_zw[NA];

// bf16 split B images, row-major [N][2K]: cols 0..K-1 = hi(W), K..2K-1 = lo(W)
__device__ __align__(16) __nv_bfloat16 g_WbP[96 * 256];
__device__ __align__(16) __nv_bfloat16 g_WbA[64 * 128];
__device__ __align__(16) float g_b1[HH], g_brev[HH], g_uc[HH], g_uw[HH], g_wr2[HH];
__device__ float g_cbias;

// ---------------- helpers ----------------
__device__ __forceinline__ uint32_t smem_u32(const void* p) {
    uint32_t a;
    asm("{ .reg .u64 t; cvta.to.shared.u64 t, %1; cvt.u32.u64 %0, t; }" : "=r"(a) : "l"(p));
    return a;
}
__device__ __forceinline__ unsigned int pack_bf16(float a, float b) {
    __nv_bfloat162 h = __floats2bfloat162_rn(a, b);
    return *reinterpret_cast<unsigned int*>(&h);
}
__device__ __forceinline__ void ldsm4(uint32_t& r0, uint32_t& r1, uint32_t& r2, uint32_t& r3,
                                      uint32_t addr) {
    asm volatile("ldmatrix.sync.aligned.m8n8.x4.shared.b16 {%0,%1,%2,%3}, [%4];"
                 : "=r"(r0), "=r"(r1), "=r"(r2), "=r"(r3) : "r"(addr));
}
__device__ __forceinline__ void mma16816(float* d, const uint32_t* a, uint32_t b0, uint32_t b1) {
    asm volatile(
        "mma.sync.aligned.m16n8k16.row.col.f32.bf16.bf16.f32 "
        "{%0,%1,%2,%3}, {%4,%5,%6,%7}, {%8,%9}, {%0,%1,%2,%3};"
        : "+f"(d[0]), "+f"(d[1]), "+f"(d[2]), "+f"(d[3])
        : "r"(a[0]), "r"(a[1]), "r"(a[2]), "r"(a[3]), "r"(b0), "r"(b1));
}

// ---------------- weight prep + degree histogram (fused; g_deg pre-zeroed) ----------------
__global__ void k_init(const float* __restrict__ W1l_c,  const float* __restrict__ b1l_c,
                       const float* __restrict__ W1r_c,  const float* __restrict__ W1l_w,
                       const float* __restrict__ b1l_w,  const float* __restrict__ W1r_w,
                       const float* __restrict__ W1l_rev,const float* __restrict__ b1l_rev,
                       const float* __restrict__ W1r_rev,const float* __restrict__ W2l_c,
                       const float* __restrict__ b2l_c,  const float* __restrict__ W2r_c,
                       const float* __restrict__ W2l_w,  const float* __restrict__ b2l_w,
                       const float* __restrict__ W2r_w,  const float* __restrict__ Wh,
                       const float* __restrict__ bh,
                       const int* __restrict__ dc, const int* __restrict__ dw,
                       const int* __restrict__ dr) {
    int b = blockIdx.x;
    if (b >= 48) {
        int e = (b - 48) * 256 + threadIdx.x;
        if (e < EE)            atomicAdd(&g_deg[__ldg(dc + e)], 1);
        else if (e < 2 * EE)   atomicAdd(&g_deg[NP + __ldg(dw + e - EE)], 1);
        else if (e < 3 * EE)   atomicAdd(&g_deg[2 * NP + __ldg(dr + e - 2 * EE)], 1);
        return;
    }
    int idx = b * 256 + threadIdx.x;
    const int stride = 48 * 256;

    for (int q = idx; q < 96 * 256; q += stride) {
        int n = q >> 8, kc = q & 255;
        int k = kc & 127;
        bool lo = kc >= 128;
        float v;
        if (n < 32)      v = W1l_c[k * HH + n];
        else if (n < 64) v = W1l_rev[k * HH + n - 32];
        else             v = W1r_c[k * HH + n - 64] + W1r_w[k * HH + n - 64];
        __nv_bfloat16 h = __float2bfloat16(v);
        g_WbP[q] = lo ? __float2bfloat16(v - __bfloat162float(h)) : h;
    }
    for (int q = idx; q < 64 * 128; q += stride) {
        int n = q >> 7, kc = q & 127;
        int k = kc & 63;
        bool lo = kc >= 64;
        float v = (n < 32) ? W1l_w[k * HH + n] : W1r_rev[k * HH + n - 32];
        __nv_bfloat16 h = __float2bfloat16(v);
        g_WbA[q] = lo ? __float2bfloat16(v - __bfloat162float(h)) : h;
    }
    if (idx < HH) {
        g_b1[idx]   = b1l_c[idx] + b1l_w[idx];
        g_brev[idx] = b1l_rev[idx];
        float uc = 0.f, uw = 0.f, wr = 0.f;
        for (int j = 0; j < HH; ++j) {
            float wh = Wh[j];
            uc += W2l_c[idx * HH + j] * wh;
            uw += W2l_w[idx * HH + j] * wh;
            wr += (W2r_c[idx * HH + j] + W2r_w[idx * HH + j]) * wh;
        }
        g_uc[idx] = uc; g_uw[idx] = uw; g_wr2[idx] = wr;
    }
    if (idx == 0) {
        float cb = bh[0];
        for (int j = 0; j < HH; ++j) cb += (b2l_c[j] + b2l_w[j]) * Wh[j];
        g_cbias = cb;
    }
}

// ---------------- CSR segment allocation ----------------
__global__ void k_alloc3() {
    __shared__ int sm[256];
    __shared__ int sbase;
    int b = blockIdx.x;
    int off, n, cidx, lb;
    if (b < 196)      { off = 0;      n = NP; cidx = 0; lb = b; }
    else if (b < 392) { off = NP;     n = NP; cidx = 1; lb = b - 196; }
    else              { off = 2 * NP; n = NA; cidx = 2; lb = b - 392; }

    int t = threadIdx.x;
    int idx0 = lb * 1024 + t * 4;
    int d0 = (idx0 + 0 < n) ? g_deg[off + idx0 + 0] : 0;
    int d1 = (idx0 + 1 < n) ? g_deg[off + idx0 + 1] : 0;
    int d2 = (idx0 + 2 < n) ? g_deg[off + idx0 + 2] : 0;
    int d3 = (idx0 + 3 < n) ? g_deg[off + idx0 + 3] : 0;
    int s = d0 + d1 + d2 + d3;
    sm[t] = s;
    __syncthreads();
    for (int o = 1; o < 256; o <<= 1) {
        int v = (t >= o) ? sm[t - o] : 0;
        __syncthreads();
        sm[t] += v;
        __syncthreads();
    }
    if (t == 255) sbase = atomicAdd(&g_cnt[cidx], sm[255]);
    __syncthreads();
    int start = sbase + sm[t] - s;
    if (idx0 + 0 < n) { g_rp[off + idx0 + 0] = start; g_cur[off + idx0 + 0] = start; start += d0; }
    if (idx0 + 1 < n) { g_rp[off + idx0 + 1] = start; g_cur[off + idx0 + 1] = start; start += d1; }
    if (idx0 + 2 < n) { g_rp[off + idx0 + 2] = start; g_cur[off + idx0 + 2] = start; start += d2; }
    if (idx0 + 3 < n) { g_rp[off + idx0 + 3] = start; g_cur[off + idx0 + 3] = start; }
}

__global__ void k_fill3(const int* __restrict__ sc, const int* __restrict__ dc,
                        const int* __restrict__ sw, const int* __restrict__ dw,
                        const int* __restrict__ sr, const int* __restrict__ dr) {
    int e = blockIdx.x * blockDim.x + threadIdx.x;
    const int* s; const int* d; int off, colOff, le;
    if (e < EE)          { s = sc; d = dc; off = 0;      colOff = 0;      le = e; }
    else if (e < 2 * EE) { s = sw; d = dw; off = NP;     colOff = EE;     le = e - EE; }
    else if (e < 3 * EE) { s = sr; d = dr; off = 2 * NP; colOff = 2 * EE; le = e - 2 * EE; }
    else return;
    int dd = __ldg(d + le);
    int p = atomicAdd(&g_cur[off + dd], 1);
    g_col[colOff + p] = __ldg(s + le);
}

// ---------------- bf16 3-term-split GEMM body ----------------
template <int K, int N, int WHICH>
__device__ __forceinline__ void gemm_body(const float* __restrict__ A,
                                          const __nv_bfloat16* __restrict__ B, // [N][2K]
                                          int M, int row0,
                                          __nv_bfloat16* As, __nv_bfloat16* Bs) {
    constexpr int CK  = 32;
    constexpr int NCH = K / CK;
    constexpr int STR = 2 * CK + 8;   // 72
    constexpr int NP2 = N / 32;
    constexpr int NT  = N / 16;

    const int tid = threadIdx.x;
    const int warp = tid >> 5, lane = tid & 31;
    const int wr = warp & 3, wc = warp >> 2;
    const int lr = lane & 7, sel = lane >> 3;
    const uint32_t As_u = smem_u32(As), Bs_u = smem_u32(Bs);

    float d[2][NT][4];
#pragma unroll
    for (int rg = 0; rg < 2; ++rg)
#pragma unroll
        for (int nt = 0; nt < NT; ++nt)
#pragma unroll
            for (int j = 0; j < 4; ++j) d[rg][nt][j] = 0.f;

#pragma unroll
    for (int ch = 0; ch < NCH; ++ch) {
        __syncthreads();
        // A chunk: 128 rows x 32 f32, split hi/lo
        {
            const int q = tid & 3, r0 = tid >> 2;
#pragma unroll
            for (int i = 0; i < 2; ++i) {
                int r = r0 + 64 * i;
                int gr = row0 + r; if (gr > M - 1) gr = M - 1;
                const float4* p = (const float4*)(A + (size_t)gr * K + ch * CK + q * 8);
                float4 va = p[0], vb = p[1];
                float f[8] = {va.x, va.y, va.z, va.w, vb.x, vb.y, vb.z, vb.w};
                float h[8], l[8];
#pragma unroll
                for (int j = 0; j < 8; ++j) {
                    h[j] = __bfloat162float(__float2bfloat16(f[j]));
                    l[j] = f[j] - h[j];
                }
                uint4 HI = {pack_bf16(h[0], h[1]), pack_bf16(h[2], h[3]),
                            pack_bf16(h[4], h[5]), pack_bf16(h[6], h[7])};
                uint4 LO = {pack_bf16(l[0], l[1]), pack_bf16(l[2], l[3]),
                            pack_bf16(l[4], l[5]), pack_bf16(l[6], l[7])};
                *(uint4*)(As + r * STR + q * 8)      = HI;
                *(uint4*)(As + r * STR + CK + q * 8) = LO;
            }
        }
        // B chunk: grp 0-3 = hi cols, 4-7 = lo cols
        for (int u = tid; u < N * 8; u += 256) {
            int n = u >> 3, grp = u & 7;
            int srcCol = (grp < 4) ? (ch * CK + grp * 8) : (K + ch * CK + (grp - 4) * 8);
            *(uint4*)(Bs + n * STR + grp * 8) = *(const uint4*)(B + n * 2 * K + srcCol);
        }
        __syncthreads();

#pragma unroll
        for (int ks = 0; ks < CK / 16; ++ks) {
            const uint32_t a_base = As_u + (uint32_t)(((wr * 32 + lr + (sel & 1) * 8) * STR +
                                                       ks * 16 + (sel >> 1) * 8) * 2);
            const uint32_t b_base = Bs_u + (uint32_t)(((wc * (N / 2) + lr + (sel >> 1) * 8) * STR +
                                                       ks * 16 + (sel & 1) * 8) * 2);
            uint32_t ah[2][4], al[2][4];
#pragma unroll
            for (int rg = 0; rg < 2; ++rg)
                ldsm4(ah[rg][0], ah[rg][1], ah[rg][2], ah[rg][3],
                      a_base + (uint32_t)(rg * 16 * STR * 2));
#pragma unroll
            for (int rg = 0; rg < 2; ++rg)
                ldsm4(al[rg][0], al[rg][1], al[rg][2], al[rg][3],
                      a_base + (uint32_t)((rg * 16 * STR + CK) * 2));
#pragma unroll
            for (int np = 0; np < NP2; ++np) {
                uint32_t b0, b1, b2, b3;
                ldsm4(b0, b1, b2, b3, b_base + (uint32_t)(np * 16 * STR * 2));
#pragma unroll
                for (int rg = 0; rg < 2; ++rg) {
                    mma16816(d[rg][2 * np],     ah[rg], b0, b1);
                    mma16816(d[rg][2 * np + 1], ah[rg], b2, b3);
                }
#pragma unroll
                for (int rg = 0; rg < 2; ++rg) {
                    mma16816(d[rg][2 * np],     al[rg], b0, b1);
                    mma16816(d[rg][2 * np + 1], al[rg], b2, b3);
                }
                ldsm4(b0, b1, b2, b3, b_base + (uint32_t)((np * 16 * STR + CK) * 2));
#pragma unroll
                for (int rg = 0; rg < 2; ++rg) {
                    mma16816(d[rg][2 * np],     ah[rg], b0, b1);
                    mma16816(d[rg][2 * np + 1], ah[rg], b2, b3);
                }
            }
        }
    }

    // epilogue -> plane-split outputs (gathered planes fp16, self planes fp32)
    const int g = lane >> 2, t = lane & 3;
#pragma unroll
    for (int rg = 0; rg < 2; ++rg) {
        const int r1 = row0 + wr * 32 + rg * 16 + g, r2 = r1 + 8;
#pragma unroll
        for (int nt = 0; nt < NT; ++nt) {
            int col = wc * (N / 2) + nt * 8 + 2 * t;
            int pl = col >> 5, cc = col & 31;
            bool fp16plane; __half* H; float* F;
            if (WHICH == 0) {
                fp16plane = (pl < 2);
                H = (pl == 0) ? g_P0 : g_P1;
                F = g_P2;
            } else {
                fp16plane = (pl == 0);
                H = g_A0;
                F = g_A1;
            }
            if (fp16plane) {
                __half2 v1 = __floats2half2_rn(d[rg][nt][0], d[rg][nt][1]);
                __half2 v2 = __floats2half2_rn(d[rg][nt][2], d[rg][nt][3]);
                if (r1 < M) *(__half2*)(H + (size_t)r1 * 32 + cc) = v1;
                if (r2 < M) *(__half2*)(H + (size_t)r2 * 32 + cc) = v2;
            } else {
                if (r1 < M) *(float2*)(F + (size_t)r1 * 32 + cc) = make_float2(d[rg][nt][0], d[rg][nt][1]);
                if (r2 < M) *(float2*)(F + (size_t)r2 * 32 + cc) = make_float2(d[rg][nt][2], d[rg][nt][3]);
            }
        }
    }
}

__global__ void __launch_bounds__(256, 2) k_gemm_all(const float* __restrict__ xp,
                                                     const float* __restrict__ xa) {
    __shared__ __nv_bfloat16 sm[128 * 72 + 96 * 72];
    if (blockIdx.x < GEMM_BLKS_P)
        gemm_body<128, 96, 0>(xp, g_WbP, NP, blockIdx.x * 128, sm, sm + 128 * 72);
    else
        gemm_body<64, 64, 1>(xa, g_WbA, NA, (blockIdx.x - GEMM_BLKS_P) * 128, sm, sm + 128 * 72);
}

// ---------------- layer-1 gathers: half-warp __half2 lanes, 2 edges/instruction ----------------
// Half h (lane>>4) handles edges e0+h+2j; lane lh (lane&15) covers feature pair (2lh, 2lh+1).
// Returns partial mean (this half's edge subset / d); halves are combined by caller via shfl_xor(16).
__device__ __forceinline__ float2 gather2(const int* __restrict__ col, int d,
                                          const __half2* __restrict__ base, int lh, int h) {
    float sx = 0.f, sy = 0.f;
    for (int e0 = 0; e0 < d; e0 += 8) {
        int idx[4];
#pragma unroll
        for (int j = 0; j < 4; ++j) {
            int e = e0 + h + 2 * j;
            idx[j] = (e < d) ? __ldg(col + e) : -1;
        }
#pragma unroll
        for (int j = 0; j < 4; ++j) {
            if (idx[j] >= 0) {
                float2 f = __half22float2(__ldg(base + (size_t)idx[j] * 16 + lh));
                sx += f.x; sy += f.y;
            }
        }
    }
    float inv = 1.f / fmaxf((float)d, 1.f);
    return make_float2(sx * inv, sy * inv);
}

__global__ void __launch_bounds__(256) k_pa() {
    int lane = threadIdx.x & 31;
    int h = lane >> 4, lh = lane & 15;
    if (blockIdx.x < PA_BLKS_P) {
        int w = blockIdx.x * 8 + (threadIdx.x >> 5);
        int s  = __ldg(&g_rp[w]);      int d  = __ldg(&g_deg[w]);
        int s2 = __ldg(&g_rp[NP + w]); int d2 = __ldg(&g_deg[NP + w]);

        float2 mc = gather2(g_col + s, d, (const __half2*)g_P0, lh, h);
        float2 mw = gather2(g_col + EE + s2, d2, (const __half2*)g_A0, lh, h);
        float2 m = make_float2(mc.x + mw.x, mc.y + mw.y);
        // combine the two half-warps' edge subsets
        m.x += __shfl_xor_sync(0xFFFFFFFFu, m.x, 16);
        m.y += __shfl_xor_sync(0xFFFFFFFFu, m.y, 16);

        float2 self = *(const float2*)(g_P2 + (size_t)w * 32 + 2 * lh);
        float2 b1   = *(const float2*)(g_b1 + 2 * lh);
        float px = fmaxf(m.x + self.x + b1.x, 0.f);
        float py = fmaxf(m.y + self.y + b1.y, 0.f);

        float2 uc2 = *(const float2*)(g_uc + 2 * lh);
        float2 wr2 = *(const float2*)(g_wr2 + 2 * lh);
        float zc = px * uc2.x + py * uc2.y;
        float zr = px * wr2.x + py * wr2.y;
#pragma unroll
        for (int o = 16; o; o >>= 1) {
            zc += __shfl_xor_sync(0xFFFFFFFFu, zc, o);
            zr += __shfl_xor_sync(0xFFFFFFFFu, zr, o);
        }
        if (lane == 0) { g_zc[w] = 0.5f * zc; g_zr[w] = 0.5f * zr; }
    } else {
        int w = (blockIdx.x - PA_BLKS_P) * 8 + (threadIdx.x >> 5);
        int s = __ldg(&g_rp[2 * NP + w]); int d = __ldg(&g_deg[2 * NP + w]);

        float2 m = gather2(g_col + 2 * EE + s, d, (const __half2*)g_P1, lh, h);
        m.x += __shfl_xor_sync(0xFFFFFFFFu, m.x, 16);
        m.y += __shfl_xor_sync(0xFFFFFFFFu, m.y, 16);

        float2 self = *(const float2*)(g_A1 + (size_t)w * 32 + 2 * lh);
        float2 br   = *(const float2*)(g_brev + 2 * lh);
        float px = fmaxf(m.x + self.x + br.x, 0.f);
        float py = fmaxf(m.y + self.y + br.y, 0.f);

        float2 uw2 = *(const float2*)(g_uw + 2 * lh);
        float zw = px * uw2.x + py * uw2.y;
#pragma unroll
        for (int o = 16; o; o >>= 1) zw += __shfl_xor_sync(0xFFFFFFFFu, zw, o);
        if (lane == 0) g_zw[w] = 0.5f * zw;
    }
}

// ---------------- layer 2 scalar aggregation + head; restores g_deg/g_cnt ----------------
__device__ __forceinline__ float gather_mean1(const int* __restrict__ col, int d,
                                              const float* __restrict__ z) {
    float acc = 0.f;
    for (int e = 0; e < d; e += 8) {
        int idx[8];
        float v[8];
#pragma unroll
        for (int j = 0; j < 8; ++j) idx[j] = (e + j < d) ? __ldg(col + e + j) : -1;
#pragma unroll
        for (int j = 0; j < 8; ++j) v[j] = (idx[j] >= 0) ? __ldg(z + idx[j]) : 0.f;
        acc += ((v[0] + v[1]) + (v[2] + v[3])) + ((v[4] + v[5]) + (v[6] + v[7]));
    }
    return acc / fmaxf((float)d, 1.f);
}

__global__ void __launch_bounds__(256) k_out(float* __restrict__ out) {
    int i = blockIdx.x * blockDim.x + threadIdx.x;
    if (i >= NP) return;
    int s  = __ldg(&g_rp[i]);      int d  = __ldg(&g_deg[i]);
    int s2 = __ldg(&g_rp[NP + i]); int d2 = __ldg(&g_deg[NP + i]);
    float sc = gather_mean1(g_col + s, d, g_zc);
    float sw = gather_mean1(g_col + EE + s2, d2, g_zw);
    out[i] = sc + sw + __ldg(&g_zr[i]) + g_cbias;
    // state restore for next graph replay
    g_deg[i] = 0;
    g_deg[NP + i] = 0;
    if (i < NA) g_deg[2 * NP + i] = 0;
    if (i < 3) g_cnt[i] = 0;
}

// ---------------- launch (serial; R12 schedule) ----------------
extern "C" void kernel_launch(void* const* d_in, const int* in_sizes, int n_in,
                              void* d_out, int out_size) {
    const float* x_paper  = (const float*)d_in[0];
    const float* x_author = (const float*)d_in[1];
    const int*   ei_c     = (const int*)d_in[2];
    const int*   ei_w     = (const int*)d_in[3];
    const int*   ei_r     = (const int*)d_in[4];
    float* out = (float*)d_out;

    k_init<<<48 + HIST_BLKS, 256>>>(
        (const float*)d_in[5],  (const float*)d_in[6],  (const float*)d_in[7],
        (const float*)d_in[8],  (const float*)d_in[9],  (const float*)d_in[10],
        (const float*)d_in[11], (const float*)d_in[12], (const float*)d_in[13],
        (const float*)d_in[14], (const float*)d_in[15], (const float*)d_in[16],
        (const float*)d_in[17], (const float*)d_in[18], (const float*)d_in[19],
        (const float*)d_in[23], (const float*)d_in[24],
        ei_c + EE, ei_w + EE, ei_r + EE);                                      // 0
    k_alloc3<<<490, 256>>>();                                                  // 1
    k_fill3<<<HIST_BLKS, 256>>>(ei_c, ei_c + EE, ei_w, ei_w + EE, ei_r, ei_r + EE); // 2
    k_gemm_all<<<GEMM_BLKS, 256>>>(x_paper, x_author);                         // 3 (profiled slot)
    k_pa<<<PA_BLKS_P + PA_BLKS_A, 256>>>();                                    // 4
    k_out<<<(NP + 255) / 256, 256>>>(out);                                     // 5
}

// round 15
// speedup vs baseline: 1.0779x; 1.0504x over previous
#include <cuda_runtime.h>
#include <cuda_bf16.h>
#include <cuda_fp16.h>
#include <cstdint>

#define NP 200000
#define NA 100000
#define EE 1000000
#define HH 32

#define GEMM_BLKS_P 1563          // (NP+127)/128
#define GEMM_BLKS_A 782           // (NA+127)/128
#define GEMM_BLKS   (GEMM_BLKS_P + GEMM_BLKS_A)
#define HIST_BLKS   11719         // (3*EE+255)/256
#define PA_BLKS_P 25000           // NP/8
#define PA_BLKS_A 12500           // NA/8

// ---------------- device scratch ----------------
// g_deg / g_cnt are ZERO at entry: zero-init at load, re-zeroed by k_out each run.
__device__ int g_deg[2 * NP + NA];
__device__ int g_cur[2 * NP + NA];
__device__ int g_rp [2 * NP + NA];
__device__ int g_cnt[3];
__device__ int g_col[3 * EE];

// plane-split projected features; gathered planes fp16, self-read planes fp32
__device__ __align__(16) __half g_P0[(size_t)NP * 32];  // x@W1l_c        (gathered)
__device__ __align__(16) __half g_P1[(size_t)NP * 32];  // x@W1l_rev      (gathered)
__device__ __align__(16) float  g_P2[(size_t)NP * 32];  // x@(W1r_c+W1r_w)(self)
__device__ __align__(16) __half g_A0[(size_t)NA * 32];  // x@W1l_w        (gathered)
__device__ __align__(16) float  g_A1[(size_t)NA * 32];  // x@W1r_rev      (self)
__device__ float g_zc[NP], g_zr[NP], g_zw[NA];

// bf16 split B images, row-major [N][2K]: cols 0..K-1 = hi(W), K..2K-1 = lo(W)
__device__ __align__(16) __nv_bfloat16 g_WbP[96 * 256];
__device__ __align__(16) __nv_bfloat16 g_WbA[64 * 128];
__device__ __align__(16) float g_b1[HH], g_brev[HH], g_uc[HH], g_uw[HH], g_wr2[HH];
__device__ float g_cbias;

// ---------------- helpers ----------------
__device__ __forceinline__ uint32_t smem_u32(const void* p) {
    uint32_t a;
    asm("{ .reg .u64 t; cvta.to.shared.u64 t, %1; cvt.u32.u64 %0, t; }" : "=r"(a) : "l"(p));
    return a;
}
__device__ __forceinline__ unsigned int pack_bf16(float a, float b) {
    __nv_bfloat162 h = __floats2bfloat162_rn(a, b);
    return *reinterpret_cast<unsigned int*>(&h);
}
__device__ __forceinline__ void ldsm4(uint32_t& r0, uint32_t& r1, uint32_t& r2, uint32_t& r3,
                                      uint32_t addr) {
    asm volatile("ldmatrix.sync.aligned.m8n8.x4.shared.b16 {%0,%1,%2,%3}, [%4];"
                 : "=r"(r0), "=r"(r1), "=r"(r2), "=r"(r3) : "r"(addr));
}
__device__ __forceinline__ void mma16816(float* d, const uint32_t* a, uint32_t b0, uint32_t b1) {
    asm volatile(
        "mma.sync.aligned.m16n8k16.row.col.f32.bf16.bf16.f32 "
        "{%0,%1,%2,%3}, {%4,%5,%6,%7}, {%8,%9}, {%0,%1,%2,%3};"
        : "+f"(d[0]), "+f"(d[1]), "+f"(d[2]), "+f"(d[3])
        : "r"(a[0]), "r"(a[1]), "r"(a[2]), "r"(a[3]), "r"(b0), "r"(b1));
}

// ---------------- weight prep + degree histogram (fused; g_deg pre-zeroed) ----------------
__global__ void k_init(const float* __restrict__ W1l_c,  const float* __restrict__ b1l_c,
                       const float* __restrict__ W1r_c,  const float* __restrict__ W1l_w,
                       const float* __restrict__ b1l_w,  const float* __restrict__ W1r_w,
                       const float* __restrict__ W1l_rev,const float* __restrict__ b1l_rev,
                       const float* __restrict__ W1r_rev,const float* __restrict__ W2l_c,
                       const float* __restrict__ b2l_c,  const float* __restrict__ W2r_c,
                       const float* __restrict__ W2l_w,  const float* __restrict__ b2l_w,
                       const float* __restrict__ W2r_w,  const float* __restrict__ Wh,
                       const float* __restrict__ bh,
                       const int* __restrict__ dc, const int* __restrict__ dw,
                       const int* __restrict__ dr) {
    int b = blockIdx.x;
    if (b >= 48) {
        int e = (b - 48) * 256 + threadIdx.x;
        if (e < EE)            atomicAdd(&g_deg[__ldg(dc + e)], 1);
        else if (e < 2 * EE)   atomicAdd(&g_deg[NP + __ldg(dw + e - EE)], 1);
        else if (e < 3 * EE)   atomicAdd(&g_deg[2 * NP + __ldg(dr + e - 2 * EE)], 1);
        return;
    }
    int idx = b * 256 + threadIdx.x;
    const int stride = 48 * 256;

    for (int q = idx; q < 96 * 256; q += stride) {
        int n = q >> 8, kc = q & 255;
        int k = kc & 127;
        bool lo = kc >= 128;
        float v;
        if (n < 32)      v = W1l_c[k * HH + n];
        else if (n < 64) v = W1l_rev[k * HH + n - 32];
        else             v = W1r_c[k * HH + n - 64] + W1r_w[k * HH + n - 64];
        __nv_bfloat16 h = __float2bfloat16(v);
        g_WbP[q] = lo ? __float2bfloat16(v - __bfloat162float(h)) : h;
    }
    for (int q = idx; q < 64 * 128; q += stride) {
        int n = q >> 7, kc = q & 127;
        int k = kc & 63;
        bool lo = kc >= 64;
        float v = (n < 32) ? W1l_w[k * HH + n] : W1r_rev[k * HH + n - 32];
        __nv_bfloat16 h = __float2bfloat16(v);
        g_WbA[q] = lo ? __float2bfloat16(v - __bfloat162float(h)) : h;
    }
    if (idx < HH) {
        g_b1[idx]   = b1l_c[idx] + b1l_w[idx];
        g_brev[idx] = b1l_rev[idx];
        float uc = 0.f, uw = 0.f, wr = 0.f;
        for (int j = 0; j < HH; ++j) {
            float wh = Wh[j];
            uc += W2l_c[idx * HH + j] * wh;
            uw += W2l_w[idx * HH + j] * wh;
            wr += (W2r_c[idx * HH + j] + W2r_w[idx * HH + j]) * wh;
        }
        g_uc[idx] = uc; g_uw[idx] = uw; g_wr2[idx] = wr;
    }
    if (idx == 0) {
        float cb = bh[0];
        for (int j = 0; j < HH; ++j) cb += (b2l_c[j] + b2l_w[j]) * Wh[j];
        g_cbias = cb;
    }
}

// ---------------- CSR segment allocation ----------------
__global__ void k_alloc3() {
    __shared__ int sm[256];
    __shared__ int sbase;
    int b = blockIdx.x;
    int off, n, cidx, lb;
    if (b < 196)      { off = 0;      n = NP; cidx = 0; lb = b; }
    else if (b < 392) { off = NP;     n = NP; cidx = 1; lb = b - 196; }
    else              { off = 2 * NP; n = NA; cidx = 2; lb = b - 392; }

    int t = threadIdx.x;
    int idx0 = lb * 1024 + t * 4;
    int d0 = (idx0 + 0 < n) ? g_deg[off + idx0 + 0] : 0;
    int d1 = (idx0 + 1 < n) ? g_deg[off + idx0 + 1] : 0;
    int d2 = (idx0 + 2 < n) ? g_deg[off + idx0 + 2] : 0;
    int d3 = (idx0 + 3 < n) ? g_deg[off + idx0 + 3] : 0;
    int s = d0 + d1 + d2 + d3;
    sm[t] = s;
    __syncthreads();
    for (int o = 1; o < 256; o <<= 1) {
        int v = (t >= o) ? sm[t - o] : 0;
        __syncthreads();
        sm[t] += v;
        __syncthreads();
    }
    if (t == 255) sbase = atomicAdd(&g_cnt[cidx], sm[255]);
    __syncthreads();
    int start = sbase + sm[t] - s;
    if (idx0 + 0 < n) { g_rp[off + idx0 + 0] = start; g_cur[off + idx0 + 0] = start; start += d0; }
    if (idx0 + 1 < n) { g_rp[off + idx0 + 1] = start; g_cur[off + idx0 + 1] = start; start += d1; }
    if (idx0 + 2 < n) { g_rp[off + idx0 + 2] = start; g_cur[off + idx0 + 2] = start; start += d2; }
    if (idx0 + 3 < n) { g_rp[off + idx0 + 3] = start; g_cur[off + idx0 + 3] = start; }
}

__global__ void k_fill3(const int* __restrict__ sc, const int* __restrict__ dc,
                        const int* __restrict__ sw, const int* __restrict__ dw,
                        const int* __restrict__ sr, const int* __restrict__ dr) {
    int e = blockIdx.x * blockDim.x + threadIdx.x;
    const int* s; const int* d; int off, colOff, le;
    if (e < EE)          { s = sc; d = dc; off = 0;      colOff = 0;      le = e; }
    else if (e < 2 * EE) { s = sw; d = dw; off = NP;     colOff = EE;     le = e - EE; }
    else if (e < 3 * EE) { s = sr; d = dr; off = 2 * NP; colOff = 2 * EE; le = e - 2 * EE; }
    else return;
    int dd = __ldg(d + le);
    int p = atomicAdd(&g_cur[off + dd], 1);
    g_col[colOff + p] = __ldg(s + le);
}

// ---------------- bf16 3-term-split GEMM body ----------------
template <int K, int N, int WHICH>
__device__ __forceinline__ void gemm_body(const float* __restrict__ A,
                                          const __nv_bfloat16* __restrict__ B, // [N][2K]
                                          int M, int row0,
                                          __nv_bfloat16* As, __nv_bfloat16* Bs) {
    constexpr int CK  = 32;
    constexpr int NCH = K / CK;
    constexpr int STR = 2 * CK + 8;   // 72
    constexpr int NP2 = N / 32;
    constexpr int NT  = N / 16;

    const int tid = threadIdx.x;
    const int warp = tid >> 5, lane = tid & 31;
    const int wr = warp & 3, wc = warp >> 2;
    const int lr = lane & 7, sel = lane >> 3;
    const uint32_t As_u = smem_u32(As), Bs_u = smem_u32(Bs);

    float d[2][NT][4];
#pragma unroll
    for (int rg = 0; rg < 2; ++rg)
#pragma unroll
        for (int nt = 0; nt < NT; ++nt)
#pragma unroll
            for (int j = 0; j < 4; ++j) d[rg][nt][j] = 0.f;

#pragma unroll
    for (int ch = 0; ch < NCH; ++ch) {
        __syncthreads();
        // A chunk: 128 rows x 32 f32, split hi/lo
        {
            const int q = tid & 3, r0 = tid >> 2;
#pragma unroll
            for (int i = 0; i < 2; ++i) {
                int r = r0 + 64 * i;
                int gr = row0 + r; if (gr > M - 1) gr = M - 1;
                const float4* p = (const float4*)(A + (size_t)gr * K + ch * CK + q * 8);
                float4 va = p[0], vb = p[1];
                float f[8] = {va.x, va.y, va.z, va.w, vb.x, vb.y, vb.z, vb.w};
                float h[8], l[8];
#pragma unroll
                for (int j = 0; j < 8; ++j) {
                    h[j] = __bfloat162float(__float2bfloat16(f[j]));
                    l[j] = f[j] - h[j];
                }
                uint4 HI = {pack_bf16(h[0], h[1]), pack_bf16(h[2], h[3]),
                            pack_bf16(h[4], h[5]), pack_bf16(h[6], h[7])};
                uint4 LO = {pack_bf16(l[0], l[1]), pack_bf16(l[2], l[3]),
                            pack_bf16(l[4], l[5]), pack_bf16(l[6], l[7])};
                *(uint4*)(As + r * STR + q * 8)      = HI;
                *(uint4*)(As + r * STR + CK + q * 8) = LO;
            }
        }
        // B chunk: grp 0-3 = hi cols, 4-7 = lo cols
        for (int u = tid; u < N * 8; u += 256) {
            int n = u >> 3, grp = u & 7;
            int srcCol = (grp < 4) ? (ch * CK + grp * 8) : (K + ch * CK + (grp - 4) * 8);
            *(uint4*)(Bs + n * STR + grp * 8) = *(const uint4*)(B + n * 2 * K + srcCol);
        }
        __syncthreads();

#pragma unroll
        for (int ks = 0; ks < CK / 16; ++ks) {
            const uint32_t a_base = As_u + (uint32_t)(((wr * 32 + lr + (sel & 1) * 8) * STR +
                                                       ks * 16 + (sel >> 1) * 8) * 2);
            const uint32_t b_base = Bs_u + (uint32_t)(((wc * (N / 2) + lr + (sel >> 1) * 8) * STR +
                                                       ks * 16 + (sel & 1) * 8) * 2);
            uint32_t ah[2][4], al[2][4];
#pragma unroll
            for (int rg = 0; rg < 2; ++rg)
                ldsm4(ah[rg][0], ah[rg][1], ah[rg][2], ah[rg][3],
                      a_base + (uint32_t)(rg * 16 * STR * 2));
#pragma unroll
            for (int rg = 0; rg < 2; ++rg)
                ldsm4(al[rg][0], al[rg][1], al[rg][2], al[rg][3],
                      a_base + (uint32_t)((rg * 16 * STR + CK) * 2));
#pragma unroll
            for (int np = 0; np < NP2; ++np) {
                uint32_t b0, b1, b2, b3;
                ldsm4(b0, b1, b2, b3, b_base + (uint32_t)(np * 16 * STR * 2));
#pragma unroll
                for (int rg = 0; rg < 2; ++rg) {
                    mma16816(d[rg][2 * np],     ah[rg], b0, b1);
                    mma16816(d[rg][2 * np + 1], ah[rg], b2, b3);
                }
#pragma unroll
                for (int rg = 0; rg < 2; ++rg) {
                    mma16816(d[rg][2 * np],     al[rg], b0, b1);
                    mma16816(d[rg][2 * np + 1], al[rg], b2, b3);
                }
                ldsm4(b0, b1, b2, b3, b_base + (uint32_t)((np * 16 * STR + CK) * 2));
#pragma unroll
                for (int rg = 0; rg < 2; ++rg) {
                    mma16816(d[rg][2 * np],     ah[rg], b0, b1);
                    mma16816(d[rg][2 * np + 1], ah[rg], b2, b3);
                }
            }
        }
    }

    // epilogue -> plane-split outputs (gathered planes fp16, self planes fp32)
    const int g = lane >> 2, t = lane & 3;
#pragma unroll
    for (int rg = 0; rg < 2; ++rg) {
        const int r1 = row0 + wr * 32 + rg * 16 + g, r2 = r1 + 8;
#pragma unroll
        for (int nt = 0; nt < NT; ++nt) {
            int col = wc * (N / 2) + nt * 8 + 2 * t;
            int pl = col >> 5, cc = col & 31;
            bool fp16plane; __half* H; float* F;
            if (WHICH == 0) {
                fp16plane = (pl < 2);
                H = (pl == 0) ? g_P0 : g_P1;
                F = g_P2;
            } else {
                fp16plane = (pl == 0);
                H = g_A0;
                F = g_A1;
            }
            if (fp16plane) {
                __half2 v1 = __floats2half2_rn(d[rg][nt][0], d[rg][nt][1]);
                __half2 v2 = __floats2half2_rn(d[rg][nt][2], d[rg][nt][3]);
                if (r1 < M) *(__half2*)(H + (size_t)r1 * 32 + cc) = v1;
                if (r2 < M) *(__half2*)(H + (size_t)r2 * 32 + cc) = v2;
            } else {
                if (r1 < M) *(float2*)(F + (size_t)r1 * 32 + cc) = make_float2(d[rg][nt][0], d[rg][nt][1]);
                if (r2 < M) *(float2*)(F + (size_t)r2 * 32 + cc) = make_float2(d[rg][nt][2], d[rg][nt][3]);
            }
        }
    }
}

// 3 CTAs/SM: 85-reg cap raises resident warps 16->24 on this latency-bound kernel
__global__ void __launch_bounds__(256, 3) k_gemm_all(const float* __restrict__ xp,
                                                     const float* __restrict__ xa) {
    __shared__ __nv_bfloat16 sm[128 * 72 + 96 * 72];
    if (blockIdx.x < GEMM_BLKS_P)
        gemm_body<128, 96, 0>(xp, g_WbP, NP, blockIdx.x * 128, sm, sm + 128 * 72);
    else
        gemm_body<64, 64, 1>(xa, g_WbA, NA, (blockIdx.x - GEMM_BLKS_P) * 128, sm, sm + 128 * 72);
}

// ---------------- layer-1 gathers: half-warp __half2 lanes, 2 edges/instruction ----------------
__device__ __forceinline__ float2 gather2(const int* __restrict__ col, int d,
                                          const __half2* __restrict__ base, int lh, int h) {
    float sx = 0.f, sy = 0.f;
    for (int e0 = 0; e0 < d; e0 += 8) {
        int idx[4];
#pragma unroll
        for (int j = 0; j < 4; ++j) {
            int e = e0 + h + 2 * j;
            idx[j] = (e < d) ? __ldg(col + e) : -1;
        }
#pragma unroll
        for (int j = 0; j < 4; ++j) {
            if (idx[j] >= 0) {
                float2 f = __half22float2(__ldg(base + (size_t)idx[j] * 16 + lh));
                sx += f.x; sy += f.y;
            }
        }
    }
    float inv = 1.f / fmaxf((float)d, 1.f);
    return make_float2(sx * inv, sy * inv);
}

__global__ void __launch_bounds__(256) k_pa() {
    int lane = threadIdx.x & 31;
    int h = lane >> 4, lh = lane & 15;
    if (blockIdx.x < PA_BLKS_P) {
        int w = blockIdx.x * 8 + (threadIdx.x >> 5);
        int s  = __ldg(&g_rp[w]);      int d  = __ldg(&g_deg[w]);
        int s2 = __ldg(&g_rp[NP + w]); int d2 = __ldg(&g_deg[NP + w]);

        float2 mc = gather2(g_col + s, d, (const __half2*)g_P0, lh, h);
        float2 mw = gather2(g_col + EE + s2, d2, (const __half2*)g_A0, lh, h);
        float2 m = make_float2(mc.x + mw.x, mc.y + mw.y);
        m.x += __shfl_xor_sync(0xFFFFFFFFu, m.x, 16);
        m.y += __shfl_xor_sync(0xFFFFFFFFu, m.y, 16);

        float2 self = *(const float2*)(g_P2 + (size_t)w * 32 + 2 * lh);
        float2 b1   = *(const float2*)(g_b1 + 2 * lh);
        float px = fmaxf(m.x + self.x + b1.x, 0.f);
        float py = fmaxf(m.y + self.y + b1.y, 0.f);

        float2 uc2 = *(const float2*)(g_uc + 2 * lh);
        float2 wr2 = *(const float2*)(g_wr2 + 2 * lh);
        float zc = px * uc2.x + py * uc2.y;
        float zr = px * wr2.x + py * wr2.y;
#pragma unroll
        for (int o = 16; o; o >>= 1) {
            zc += __shfl_xor_sync(0xFFFFFFFFu, zc, o);
            zr += __shfl_xor_sync(0xFFFFFFFFu, zr, o);
        }
        if (lane == 0) { g_zc[w] = 0.5f * zc; g_zr[w] = 0.5f * zr; }
    } else {
        int w = (blockIdx.x - PA_BLKS_P) * 8 + (threadIdx.x >> 5);
        int s = __ldg(&g_rp[2 * NP + w]); int d = __ldg(&g_deg[2 * NP + w]);

        float2 m = gather2(g_col + 2 * EE + s, d, (const __half2*)g_P1, lh, h);
        m.x += __shfl_xor_sync(0xFFFFFFFFu, m.x, 16);
        m.y += __shfl_xor_sync(0xFFFFFFFFu, m.y, 16);

        float2 self = *(const float2*)(g_A1 + (size_t)w * 32 + 2 * lh);
        float2 br   = *(const float2*)(g_brev + 2 * lh);
        float px = fmaxf(m.x + self.x + br.x, 0.f);
        float py = fmaxf(m.y + self.y + br.y, 0.f);

        float2 uw2 = *(const float2*)(g_uw + 2 * lh);
        float zw = px * uw2.x + py * uw2.y;
#pragma unroll
        for (int o = 16; o; o >>= 1) zw += __shfl_xor_sync(0xFFFFFFFFu, zw, o);
        if (lane == 0) g_zw[w] = 0.5f * zw;
    }
}

// ---------------- layer 2 scalar aggregation + head; restores g_deg/g_cnt ----------------
__device__ __forceinline__ float gather_mean1(const int* __restrict__ col, int d,
                                              const float* __restrict__ z) {
    float acc = 0.f;
    for (int e = 0; e < d; e += 8) {
        int idx[8];
        float v[8];
#pragma unroll
        for (int j = 0; j < 8; ++j) idx[j] = (e + j < d) ? __ldg(col + e + j) : -1;
#pragma unroll
        for (int j = 0; j < 8; ++j) v[j] = (idx[j] >= 0) ? __ldg(z + idx[j]) : 0.f;
        acc += ((v[0] + v[1]) + (v[2] + v[3])) + ((v[4] + v[5]) + (v[6] + v[7]));
    }
    return acc / fmaxf((float)d, 1.f);
}

__global__ void __launch_bounds__(256) k_out(float* __restrict__ out) {
    int i = blockIdx.x * blockDim.x + threadIdx.x;
    if (i >= NP) return;
    int s  = __ldg(&g_rp[i]);      int d  = __ldg(&g_deg[i]);
    int s2 = __ldg(&g_rp[NP + i]); int d2 = __ldg(&g_deg[NP + i]);
    float sc = gather_mean1(g_col + s, d, g_zc);
    float sw = gather_mean1(g_col + EE + s2, d2, g_zw);
    out[i] = sc + sw + __ldg(&g_zr[i]) + g_cbias;
    // state restore for next graph replay
    g_deg[i] = 0;
    g_deg[NP + i] = 0;
    if (i < NA) g_deg[2 * NP + i] = 0;
    if (i < 3) g_cnt[i] = 0;
}

// ---------------- launch ----------------
extern "C" void kernel_launch(void* const* d_in, const int* in_sizes, int n_in,
                              void* d_out, int out_size) {
    const float* x_paper  = (const float*)d_in[0];
    const float* x_author = (const float*)d_in[1];
    const int*   ei_c     = (const int*)d_in[2];
    const int*   ei_w     = (const int*)d_in[3];
    const int*   ei_r     = (const int*)d_in[4];
    float* out = (float*)d_out;

    k_init<<<48 + HIST_BLKS, 256>>>(
        (const float*)d_in[5],  (const float*)d_in[6],  (const float*)d_in[7],
        (const float*)d_in[8],  (const float*)d_in[9],  (const float*)d_in[10],
        (const float*)d_in[11], (const float*)d_in[12], (const float*)d_in[13],
        (const float*)d_in[14], (const float*)d_in[15], (const float*)d_in[16],
        (const float*)d_in[17], (const float*)d_in[18], (const float*)d_in[19],
        (const float*)d_in[23], (const float*)d_in[24],
        ei_c + EE, ei_w + EE, ei_r + EE);                                      // 0
    k_alloc3<<<490, 256>>>();                                                  // 1
    k_fill3<<<HIST_BLKS, 256>>>(ei_c, ei_c + EE, ei_w, ei_w + EE, ei_r, ei_r + EE); // 2
    k_gemm_all<<<GEMM_BLKS, 256>>>(x_paper, x_author);                         // 3 (profiled slot)
    k_pa<<<PA_BLKS_P + PA_BLKS_A, 256>>>();                                    // 4
    k_out<<<(NP + 255) / 256, 256>>>(out);                                     // 5
}

// round 16
// speedup vs baseline: 1.0891x; 1.0104x over previous
#include <cuda_runtime.h>
#include <cuda_bf16.h>
#include <cuda_fp16.h>
#include <cstdint>

#define NP 200000
#define NA 100000
#define EE 1000000
#define HH 32

#define GEMM_BLKS_P 1563          // (NP+127)/128
#define GEMM_BLKS_A 782           // (NA+127)/128
#define GEMM_BLKS   (GEMM_BLKS_P + GEMM_BLKS_A)
#define HIST_BLKS   11719         // (3*EE+255)/256
#define PA_BLKS_P 25000           // NP/8
#define PA_BLKS_A 12500           // NA/8

// ---------------- device scratch ----------------
// g_deg / g_cnt are ZERO at entry: zero-init at load, re-zeroed by k_out each run.
__device__ int g_deg[2 * NP + NA];
__device__ int g_rp [2 * NP + NA];
__device__ int g_cnt[3];
__device__ int g_rank[3 * EE];    // per-edge within-segment rank (from hist atomic)
__device__ int g_col[3 * EE];

// plane-split projected features; gathered planes fp16, self-read planes fp32
__device__ __align__(16) __half g_P0[(size_t)NP * 32];  // x@W1l_c        (gathered)
__device__ __align__(16) __half g_P1[(size_t)NP * 32];  // x@W1l_rev      (gathered)
__device__ __align__(16) float  g_P2[(size_t)NP * 32];  // x@(W1r_c+W1r_w)(self)
__device__ __align__(16) __half g_A0[(size_t)NA * 32];  // x@W1l_w        (gathered)
__device__ __align__(16) float  g_A1[(size_t)NA * 32];  // x@W1r_rev      (self)
__device__ float g_zc[NP], g_zr[NP], g_zw[NA];

// bf16 split B images, row-major [N][2K]: cols 0..K-1 = hi(W), K..2K-1 = lo(W)
__device__ __align__(16) __nv_bfloat16 g_WbP[96 * 256];
__device__ __align__(16) __nv_bfloat16 g_WbA[64 * 128];
__device__ __align__(16) float g_b1[HH], g_brev[HH], g_uc[HH], g_uw[HH], g_wr2[HH];
__device__ float g_cbias;

// ---------------- helpers ----------------
__device__ __forceinline__ uint32_t smem_u32(const void* p) {
    uint32_t a;
    asm("{ .reg .u64 t; cvta.to.shared.u64 t, %1; cvt.u32.u64 %0, t; }" : "=r"(a) : "l"(p));
    return a;
}
__device__ __forceinline__ unsigned int pack_bf16(float a, float b) {
    __nv_bfloat162 h = __floats2bfloat162_rn(a, b);
    return *reinterpret_cast<unsigned int*>(&h);
}
__device__ __forceinline__ void ldsm4(uint32_t& r0, uint32_t& r1, uint32_t& r2, uint32_t& r3,
                                      uint32_t addr) {
    asm volatile("ldmatrix.sync.aligned.m8n8.x4.shared.b16 {%0,%1,%2,%3}, [%4];"
                 : "=r"(r0), "=r"(r1), "=r"(r2), "=r"(r3) : "r"(addr));
}
__device__ __forceinline__ void mma16816(float* d, const uint32_t* a, uint32_t b0, uint32_t b1) {
    asm volatile(
        "mma.sync.aligned.m16n8k16.row.col.f32.bf16.bf16.f32 "
        "{%0,%1,%2,%3}, {%4,%5,%6,%7}, {%8,%9}, {%0,%1,%2,%3};"
        : "+f"(d[0]), "+f"(d[1]), "+f"(d[2]), "+f"(d[3])
        : "r"(a[0]), "r"(a[1]), "r"(a[2]), "r"(a[3]), "r"(b0), "r"(b1));
}

// ---------------- weight prep (main stream) ----------------
__global__ void k_prep(const float* __restrict__ W1l_c,  const float* __restrict__ b1l_c,
                       const float* __restrict__ W1r_c,  const float* __restrict__ W1l_w,
                       const float* __restrict__ b1l_w,  const float* __restrict__ W1r_w,
                       const float* __restrict__ W1l_rev,const float* __restrict__ b1l_rev,
                       const float* __restrict__ W1r_rev,const float* __restrict__ W2l_c,
                       const float* __restrict__ b2l_c,  const float* __restrict__ W2r_c,
                       const float* __restrict__ W2l_w,  const float* __restrict__ b2l_w,
                       const float* __restrict__ W2r_w,  const float* __restrict__ Wh,
                       const float* __restrict__ bh) {
    int idx = blockIdx.x * 256 + threadIdx.x;
    const int stride = 48 * 256;

    for (int q = idx; q < 96 * 256; q += stride) {
        int n = q >> 8, kc = q & 255;
        int k = kc & 127;
        bool lo = kc >= 128;
        float v;
        if (n < 32)      v = W1l_c[k * HH + n];
        else if (n < 64) v = W1l_rev[k * HH + n - 32];
        else             v = W1r_c[k * HH + n - 64] + W1r_w[k * HH + n - 64];
        __nv_bfloat16 h = __float2bfloat16(v);
        g_WbP[q] = lo ? __float2bfloat16(v - __bfloat162float(h)) : h;
    }
    for (int q = idx; q < 64 * 128; q += stride) {
        int n = q >> 7, kc = q & 127;
        int k = kc & 63;
        bool lo = kc >= 64;
        float v = (n < 32) ? W1l_w[k * HH + n] : W1r_rev[k * HH + n - 32];
        __nv_bfloat16 h = __float2bfloat16(v);
        g_WbA[q] = lo ? __float2bfloat16(v - __bfloat162float(h)) : h;
    }
    if (idx < HH) {
        g_b1[idx]   = b1l_c[idx] + b1l_w[idx];
        g_brev[idx] = b1l_rev[idx];
        float uc = 0.f, uw = 0.f, wr = 0.f;
        for (int j = 0; j < HH; ++j) {
            float wh = Wh[j];
            uc += W2l_c[idx * HH + j] * wh;
            uw += W2l_w[idx * HH + j] * wh;
            wr += (W2r_c[idx * HH + j] + W2r_w[idx * HH + j]) * wh;
        }
        g_uc[idx] = uc; g_uw[idx] = uw; g_wr2[idx] = wr;
    }
    if (idx == 0) {
        float cb = bh[0];
        for (int j = 0; j < HH; ++j) cb += (b2l_c[j] + b2l_w[j]) * Wh[j];
        g_cbias = cb;
    }
}

// ---------------- CSR build (side stream) ----------------
// hist: atomic yields each edge's within-segment rank; stored for atomic-free fill
__global__ void k_hist3(const int* __restrict__ dc, const int* __restrict__ dw,
                        const int* __restrict__ dr) {
    int e = blockIdx.x * blockDim.x + threadIdx.x;
    int off, le; const int* d;
    if (e < EE)          { d = dc; off = 0;      le = e; }
    else if (e < 2 * EE) { d = dw; off = NP;     le = e - EE; }
    else if (e < 3 * EE) { d = dr; off = 2 * NP; le = e - 2 * EE; }
    else return;
    int dd = __ldg(d + le);
    g_rank[e] = atomicAdd(&g_deg[off + dd], 1);
}

__global__ void k_alloc3() {
    __shared__ int sm[256];
    __shared__ int sbase;
    int b = blockIdx.x;
    int off, n, cidx, lb;
    if (b < 196)      { off = 0;      n = NP; cidx = 0; lb = b; }
    else if (b < 392) { off = NP;     n = NP; cidx = 1; lb = b - 196; }
    else              { off = 2 * NP; n = NA; cidx = 2; lb = b - 392; }

    int t = threadIdx.x;
    int idx0 = lb * 1024 + t * 4;
    int d0 = (idx0 + 0 < n) ? g_deg[off + idx0 + 0] : 0;
    int d1 = (idx0 + 1 < n) ? g_deg[off + idx0 + 1] : 0;
    int d2 = (idx0 + 2 < n) ? g_deg[off + idx0 + 2] : 0;
    int d3 = (idx0 + 3 < n) ? g_deg[off + idx0 + 3] : 0;
    int s = d0 + d1 + d2 + d3;
    sm[t] = s;
    __syncthreads();
    for (int o = 1; o < 256; o <<= 1) {
        int v = (t >= o) ? sm[t - o] : 0;
        __syncthreads();
        sm[t] += v;
        __syncthreads();
    }
    if (t == 255) sbase = atomicAdd(&g_cnt[cidx], sm[255]);
    __syncthreads();
    int start = sbase + sm[t] - s;
    if (idx0 + 0 < n) { g_rp[off + idx0 + 0] = start; start += d0; }
    if (idx0 + 1 < n) { g_rp[off + idx0 + 1] = start; start += d1; }
    if (idx0 + 2 < n) { g_rp[off + idx0 + 2] = start; start += d2; }
    if (idx0 + 3 < n) { g_rp[off + idx0 + 3] = start; }
}

// atomic-free fill using precomputed ranks
__global__ void k_fill3(const int* __restrict__ sc, const int* __restrict__ dc,
                        const int* __restrict__ sw, const int* __restrict__ dw,
                        const int* __restrict__ sr, const int* __restrict__ dr) {
    int e = blockIdx.x * blockDim.x + threadIdx.x;
    const int* s; const int* d; int off, colOff, le;
    if (e < EE)          { s = sc; d = dc; off = 0;      colOff = 0;      le = e; }
    else if (e < 2 * EE) { s = sw; d = dw; off = NP;     colOff = EE;     le = e - EE; }
    else if (e < 3 * EE) { s = sr; d = dr; off = 2 * NP; colOff = 2 * EE; le = e - 2 * EE; }
    else return;
    int dd = __ldg(d + le);
    int p = __ldg(&g_rp[off + dd]) + g_rank[e];
    g_col[colOff + p] = __ldg(s + le);
}

// ---------------- bf16 3-term-split GEMM body ----------------
template <int K, int N, int WHICH>
__device__ __forceinline__ void gemm_body(const float* __restrict__ A,
                                          const __nv_bfloat16* __restrict__ B, // [N][2K]
                                          int M, int row0,
                                          __nv_bfloat16* As, __nv_bfloat16* Bs) {
    constexpr int CK  = 32;
    constexpr int NCH = K / CK;
    constexpr int STR = 2 * CK + 8;   // 72
    constexpr int NP2 = N / 32;
    constexpr int NT  = N / 16;

    const int tid = threadIdx.x;
    const int warp = tid >> 5, lane = tid & 31;
    const int wr = warp & 3, wc = warp >> 2;
    const int lr = lane & 7, sel = lane >> 3;
    const uint32_t As_u = smem_u32(As), Bs_u = smem_u32(Bs);

    float d[2][NT][4];
#pragma unroll
    for (int rg = 0; rg < 2; ++rg)
#pragma unroll
        for (int nt = 0; nt < NT; ++nt)
#pragma unroll
            for (int j = 0; j < 4; ++j) d[rg][nt][j] = 0.f;

#pragma unroll
    for (int ch = 0; ch < NCH; ++ch) {
        __syncthreads();
        // A chunk: 128 rows x 32 f32, split hi/lo
        {
            const int q = tid & 3, r0 = tid >> 2;
#pragma unroll
            for (int i = 0; i < 2; ++i) {
                int r = r0 + 64 * i;
                int gr = row0 + r; if (gr > M - 1) gr = M - 1;
                const float4* p = (const float4*)(A + (size_t)gr * K + ch * CK + q * 8);
                float4 va = p[0], vb = p[1];
                float f[8] = {va.x, va.y, va.z, va.w, vb.x, vb.y, vb.z, vb.w};
                float h[8], l[8];
#pragma unroll
                for (int j = 0; j < 8; ++j) {
                    h[j] = __bfloat162float(__float2bfloat16(f[j]));
                    l[j] = f[j] - h[j];
                }
                uint4 HI = {pack_bf16(h[0], h[1]), pack_bf16(h[2], h[3]),
                            pack_bf16(h[4], h[5]), pack_bf16(h[6], h[7])};
                uint4 LO = {pack_bf16(l[0], l[1]), pack_bf16(l[2], l[3]),
                            pack_bf16(l[4], l[5]), pack_bf16(l[6], l[7])};
                *(uint4*)(As + r * STR + q * 8)      = HI;
                *(uint4*)(As + r * STR + CK + q * 8) = LO;
            }
        }
        // B chunk: grp 0-3 = hi cols, 4-7 = lo cols
        for (int u = tid; u < N * 8; u += 256) {
            int n = u >> 3, grp = u & 7;
            int srcCol = (grp < 4) ? (ch * CK + grp * 8) : (K + ch * CK + (grp - 4) * 8);
            *(uint4*)(Bs + n * STR + grp * 8) = *(const uint4*)(B + n * 2 * K + srcCol);
        }
        __syncthreads();

#pragma unroll
        for (int ks = 0; ks < CK / 16; ++ks) {
            const uint32_t a_base = As_u + (uint32_t)(((wr * 32 + lr + (sel & 1) * 8) * STR +
                                                       ks * 16 + (sel >> 1) * 8) * 2);
            const uint32_t b_base = Bs_u + (uint32_t)(((wc * (N / 2) + lr + (sel >> 1) * 8) * STR +
                                                       ks * 16 + (sel & 1) * 8) * 2);
            uint32_t ah[2][4], al[2][4];
#pragma unroll
            for (int rg = 0; rg < 2; ++rg)
                ldsm4(ah[rg][0], ah[rg][1], ah[rg][2], ah[rg][3],
                      a_base + (uint32_t)(rg * 16 * STR * 2));
#pragma unroll
            for (int rg = 0; rg < 2; ++rg)
                ldsm4(al[rg][0], al[rg][1], al[rg][2], al[rg][3],
                      a_base + (uint32_t)((rg * 16 * STR + CK) * 2));
#pragma unroll
            for (int np = 0; np < NP2; ++np) {
                uint32_t b0, b1, b2, b3;
                ldsm4(b0, b1, b2, b3, b_base + (uint32_t)(np * 16 * STR * 2));
#pragma unroll
                for (int rg = 0; rg < 2; ++rg) {
                    mma16816(d[rg][2 * np],     ah[rg], b0, b1);
                    mma16816(d[rg][2 * np + 1], ah[rg], b2, b3);
                }
#pragma unroll
                for (int rg = 0; rg < 2; ++rg) {
                    mma16816(d[rg][2 * np],     al[rg], b0, b1);
                    mma16816(d[rg][2 * np + 1], al[rg], b2, b3);
                }
                ldsm4(b0, b1, b2, b3, b_base + (uint32_t)((np * 16 * STR + CK) * 2));
#pragma unroll
                for (int rg = 0; rg < 2; ++rg) {
                    mma16816(d[rg][2 * np],     ah[rg], b0, b1);
                    mma16816(d[rg][2 * np + 1], ah[rg], b2, b3);
                }
            }
        }
    }

    // epilogue -> plane-split outputs (gathered planes fp16, self planes fp32)
    const int g = lane >> 2, t = lane & 3;
#pragma unroll
    for (int rg = 0; rg < 2; ++rg) {
        const int r1 = row0 + wr * 32 + rg * 16 + g, r2 = r1 + 8;
#pragma unroll
        for (int nt = 0; nt < NT; ++nt) {
            int col = wc * (N / 2) + nt * 8 + 2 * t;
            int pl = col >> 5, cc = col & 31;
            bool fp16plane; __half* H; float* F;
            if (WHICH == 0) {
                fp16plane = (pl < 2);
                H = (pl == 0) ? g_P0 : g_P1;
                F = g_P2;
            } else {
                fp16plane = (pl == 0);
                H = g_A0;
                F = g_A1;
            }
            if (fp16plane) {
                __half2 v1 = __floats2half2_rn(d[rg][nt][0], d[rg][nt][1]);
                __half2 v2 = __floats2half2_rn(d[rg][nt][2], d[rg][nt][3]);
                if (r1 < M) *(__half2*)(H + (size_t)r1 * 32 + cc) = v1;
                if (r2 < M) *(__half2*)(H + (size_t)r2 * 32 + cc) = v2;
            } else {
                if (r1 < M) *(float2*)(F + (size_t)r1 * 32 + cc) = make_float2(d[rg][nt][0], d[rg][nt][1]);
                if (r2 < M) *(float2*)(F + (size_t)r2 * 32 + cc) = make_float2(d[rg][nt][2], d[rg][nt][3]);
            }
        }
    }
}

// 3 CTAs/SM (80 regs) -> 4096-reg slack per SM for co-resident CSR blocks
__global__ void __launch_bounds__(256, 3) k_gemm_all(const float* __restrict__ xp,
                                                     const float* __restrict__ xa) {
    __shared__ __nv_bfloat16 sm[128 * 72 + 96 * 72];
    if (blockIdx.x < GEMM_BLKS_P)
        gemm_body<128, 96, 0>(xp, g_WbP, NP, blockIdx.x * 128, sm, sm + 128 * 72);
    else
        gemm_body<64, 64, 1>(xa, g_WbA, NA, (blockIdx.x - GEMM_BLKS_P) * 128, sm, sm + 128 * 72);
}

// ---------------- layer-1 gathers: half-warp __half2 lanes ----------------
__device__ __forceinline__ float2 gather2(const int* __restrict__ col, int d,
                                          const __half2* __restrict__ base, int lh, int h) {
    float sx = 0.f, sy = 0.f;
    for (int e0 = 0; e0 < d; e0 += 8) {
        int idx[4];
#pragma unroll
        for (int j = 0; j < 4; ++j) {
            int e = e0 + h + 2 * j;
            idx[j] = (e < d) ? __ldg(col + e) : -1;
        }
#pragma unroll
        for (int j = 0; j < 4; ++j) {
            if (idx[j] >= 0) {
                float2 f = __half22float2(__ldg(base + (size_t)idx[j] * 16 + lh));
                sx += f.x; sy += f.y;
            }
        }
    }
    float inv = 1.f / fmaxf((float)d, 1.f);
    return make_float2(sx * inv, sy * inv);
}

__global__ void __launch_bounds__(256) k_pa() {
    int lane = threadIdx.x & 31;
    int h = lane >> 4, lh = lane & 15;
    if (blockIdx.x < PA_BLKS_P) {
        int w = blockIdx.x * 8 + (threadIdx.x >> 5);
        int s  = __ldg(&g_rp[w]);      int d  = __ldg(&g_deg[w]);
        int s2 = __ldg(&g_rp[NP + w]); int d2 = __ldg(&g_deg[NP + w]);

        float2 mc = gather2(g_col + s, d, (const __half2*)g_P0, lh, h);
        float2 mw = gather2(g_col + EE + s2, d2, (const __half2*)g_A0, lh, h);
        float2 m = make_float2(mc.x + mw.x, mc.y + mw.y);
        m.x += __shfl_xor_sync(0xFFFFFFFFu, m.x, 16);
        m.y += __shfl_xor_sync(0xFFFFFFFFu, m.y, 16);

        float2 self = *(const float2*)(g_P2 + (size_t)w * 32 + 2 * lh);
        float2 b1   = *(const float2*)(g_b1 + 2 * lh);
        float px = fmaxf(m.x + self.x + b1.x, 0.f);
        float py = fmaxf(m.y + self.y + b1.y, 0.f);

        float2 uc2 = *(const float2*)(g_uc + 2 * lh);
        float2 wr2 = *(const float2*)(g_wr2 + 2 * lh);
        float zc = px * uc2.x + py * uc2.y;
        float zr = px * wr2.x + py * wr2.y;
#pragma unroll
        for (int o = 16; o; o >>= 1) {
            zc += __shfl_xor_sync(0xFFFFFFFFu, zc, o);
            zr += __shfl_xor_sync(0xFFFFFFFFu, zr, o);
        }
        if (lane == 0) { g_zc[w] = 0.5f * zc; g_zr[w] = 0.5f * zr; }
    } else {
        int w = (blockIdx.x - PA_BLKS_P) * 8 + (threadIdx.x >> 5);
        int s = __ldg(&g_rp[2 * NP + w]); int d = __ldg(&g_deg[2 * NP + w]);

        float2 m = gather2(g_col + 2 * EE + s, d, (const __half2*)g_P1, lh, h);
        m.x += __shfl_xor_sync(0xFFFFFFFFu, m.x, 16);
        m.y += __shfl_xor_sync(0xFFFFFFFFu, m.y, 16);

        float2 self = *(const float2*)(g_A1 + (size_t)w * 32 + 2 * lh);
        float2 br   = *(const float2*)(g_brev + 2 * lh);
        float px = fmaxf(m.x + self.x + br.x, 0.f);
        float py = fmaxf(m.y + self.y + br.y, 0.f);

        float2 uw2 = *(const float2*)(g_uw + 2 * lh);
        float zw = px * uw2.x + py * uw2.y;
#pragma unroll
        for (int o = 16; o; o >>= 1) zw += __shfl_xor_sync(0xFFFFFFFFu, zw, o);
        if (lane == 0) g_zw[w] = 0.5f * zw;
    }
}

// ---------------- layer 2 scalar aggregation + head; restores g_deg/g_cnt ----------------
__device__ __forceinline__ float gather_mean1(const int* __restrict__ col, int d,
                                              const float* __restrict__ z) {
    float acc = 0.f;
    for (int e = 0; e < d; e += 8) {
        int idx[8];
        float v[8];
#pragma unroll
        for (int j = 0; j < 8; ++j) idx[j] = (e + j < d) ? __ldg(col + e + j) : -1;
#pragma unroll
        for (int j = 0; j < 8; ++j) v[j] = (idx[j] >= 0) ? __ldg(z + idx[j]) : 0.f;
        acc += ((v[0] + v[1]) + (v[2] + v[3])) + ((v[4] + v[5]) + (v[6] + v[7]));
    }
    return acc / fmaxf((float)d, 1.f);
}

__global__ void __launch_bounds__(256) k_out(float* __restrict__ out) {
    int i = blockIdx.x * blockDim.x + threadIdx.x;
    if (i >= NP) return;
    int s  = __ldg(&g_rp[i]);      int d  = __ldg(&g_deg[i]);
    int s2 = __ldg(&g_rp[NP + i]); int d2 = __ldg(&g_deg[NP + i]);
    float sc = gather_mean1(g_col + s, d, g_zc);
    float sw = gather_mean1(g_col + EE + s2, d2, g_zw);
    out[i] = sc + sw + __ldg(&g_zr[i]) + g_cbias;
    // state restore for next graph replay
    g_deg[i] = 0;
    g_deg[NP + i] = 0;
    if (i < NA) g_deg[2 * NP + i] = 0;
    if (i < 3) g_cnt[i] = 0;
}

// ---------------- launch: fork/join (retry; GEMM now leaves 4K-reg slack) ----------------
extern "C" void kernel_launch(void* const* d_in, const int* in_sizes, int n_in,
                              void* d_out, int out_size) {
    const float* x_paper  = (const float*)d_in[0];
    const float* x_author = (const float*)d_in[1];
    const int*   ei_c     = (const int*)d_in[2];
    const int*   ei_w     = (const int*)d_in[3];
    const int*   ei_r     = (const int*)d_in[4];
    float* out = (float*)d_out;

    static cudaStream_t s_side = nullptr;
    static cudaEvent_t s_evF = nullptr, s_evJ = nullptr;
    if (s_side == nullptr) {
        cudaStreamCreateWithFlags(&s_side, cudaStreamNonBlocking);
        cudaEventCreateWithFlags(&s_evF, cudaEventDisableTiming);
        cudaEventCreateWithFlags(&s_evJ, cudaEventDisableTiming);
    }

    // fork
    cudaEventRecord(s_evF, 0);
    cudaStreamWaitEvent(s_side, s_evF, 0);

    // side branch: CSR build (lean, L2-bound; co-residency via the GEMM's reg slack + tail waves)
    k_hist3<<<HIST_BLKS, 256, 0, s_side>>>(ei_c + EE, ei_w + EE, ei_r + EE);
    k_alloc3<<<490, 256, 0, s_side>>>();
    k_fill3<<<HIST_BLKS, 256, 0, s_side>>>(ei_c, ei_c + EE, ei_w, ei_w + EE, ei_r, ei_r + EE);
    cudaEventRecord(s_evJ, s_side);

    // main branch: weight prep + projection GEMM
    k_prep<<<48, 256>>>(
        (const float*)d_in[5],  (const float*)d_in[6],  (const float*)d_in[7],
        (const float*)d_in[8],  (const float*)d_in[9],  (const float*)d_in[10],
        (const float*)d_in[11], (const float*)d_in[12], (const float*)d_in[13],
        (const float*)d_in[14], (const float*)d_in[15], (const float*)d_in[16],
        (const float*)d_in[17], (const float*)d_in[18], (const float*)d_in[19],
        (const float*)d_in[23], (const float*)d_in[24]);
    k_gemm_all<<<GEMM_BLKS, 256>>>(x_paper, x_author);

    // join
    cudaStreamWaitEvent(0, s_evJ, 0);
    k_pa<<<PA_BLKS_P + PA_BLKS_A, 256>>>();
    k_out<<<(NP + 255) / 256, 256>>>(out);
}

// round 17
// speedup vs baseline: 1.1050x; 1.0146x over previous
#include <cuda_runtime.h>
#include <cuda_bf16.h>
#include <cuda_fp16.h>
#include <cstdint>

#define NP 200000
#define NA 100000
#define EE 1000000
#define HH 32

#define GEMM_BLKS_P 1563          // (NP+127)/128
#define GEMM_BLKS_A 782           // (NA+127)/128
#define GEMM_BLKS   (GEMM_BLKS_P + GEMM_BLKS_A)
#define H4_BLKS     2930          // (3*EE/4 + 255)/256
#define PA_BLKS_P 25000           // NP/8
#define PA_BLKS_A 12500           // NA/8

// ---------------- device scratch ----------------
// g_deg / g_cnt are ZERO at entry: zero-init at load, re-zeroed by k_out each run.
__device__ int g_deg[2 * NP + NA];
__device__ int g_rp [2 * NP + NA];
__device__ int g_cnt[3];
__device__ __align__(16) int g_rank[3 * EE];   // per-edge within-segment rank
__device__ int g_col[3 * EE];

// plane-split projected features; gathered planes fp16, self-read planes fp32
__device__ __align__(16) __half g_P0[(size_t)NP * 32];  // x@W1l_c        (gathered)
__device__ __align__(16) __half g_P1[(size_t)NP * 32];  // x@W1l_rev      (gathered)
__device__ __align__(16) float  g_P2[(size_t)NP * 32];  // x@(W1r_c+W1r_w)(self)
__device__ __align__(16) __half g_A0[(size_t)NA * 32];  // x@W1l_w        (gathered)
__device__ __align__(16) float  g_A1[(size_t)NA * 32];  // x@W1r_rev      (self)
__device__ float g_zc[NP], g_zr[NP], g_zw[NA];

// bf16 split B images, row-major [N][2K]: cols 0..K-1 = hi(W), K..2K-1 = lo(W)
__device__ __align__(16) __nv_bfloat16 g_WbP[96 * 256];
__device__ __align__(16) __nv_bfloat16 g_WbA[64 * 128];
__device__ __align__(16) float g_b1[HH], g_brev[HH], g_uc[HH], g_uw[HH], g_wr2[HH];
__device__ float g_cbias;

// ---------------- helpers ----------------
__device__ __forceinline__ uint32_t smem_u32(const void* p) {
    uint32_t a;
    asm("{ .reg .u64 t; cvta.to.shared.u64 t, %1; cvt.u32.u64 %0, t; }" : "=r"(a) : "l"(p));
    return a;
}
__device__ __forceinline__ unsigned int pack_bf16(float a, float b) {
    __nv_bfloat162 h = __floats2bfloat162_rn(a, b);
    return *reinterpret_cast<unsigned int*>(&h);
}
__device__ __forceinline__ void ldsm4(uint32_t& r0, uint32_t& r1, uint32_t& r2, uint32_t& r3,
                                      uint32_t addr) {
    asm volatile("ldmatrix.sync.aligned.m8n8.x4.shared.b16 {%0,%1,%2,%3}, [%4];"
                 : "=r"(r0), "=r"(r1), "=r"(r2), "=r"(r3) : "r"(addr));
}
__device__ __forceinline__ void mma16816(float* d, const uint32_t* a, uint32_t b0, uint32_t b1) {
    asm volatile(
        "mma.sync.aligned.m16n8k16.row.col.f32.bf16.bf16.f32 "
        "{%0,%1,%2,%3}, {%4,%5,%6,%7}, {%8,%9}, {%0,%1,%2,%3};"
        : "+f"(d[0]), "+f"(d[1]), "+f"(d[2]), "+f"(d[3])
        : "r"(a[0]), "r"(a[1]), "r"(a[2]), "r"(a[3]), "r"(b0), "r"(b1));
}

// ---------------- weight prep (main stream) ----------------
__global__ void k_prep(const float* __restrict__ W1l_c,  const float* __restrict__ b1l_c,
                       const float* __restrict__ W1r_c,  const float* __restrict__ W1l_w,
                       const float* __restrict__ b1l_w,  const float* __restrict__ W1r_w,
                       const float* __restrict__ W1l_rev,const float* __restrict__ b1l_rev,
                       const float* __restrict__ W1r_rev,const float* __restrict__ W2l_c,
                       const float* __restrict__ b2l_c,  const float* __restrict__ W2r_c,
                       const float* __restrict__ W2l_w,  const float* __restrict__ b2l_w,
                       const float* __restrict__ W2r_w,  const float* __restrict__ Wh,
                       const float* __restrict__ bh) {
    int idx = blockIdx.x * 256 + threadIdx.x;
    const int stride = 48 * 256;

    for (int q = idx; q < 96 * 256; q += stride) {
        int n = q >> 8, kc = q & 255;
        int k = kc & 127;
        bool lo = kc >= 128;
        float v;
        if (n < 32)      v = W1l_c[k * HH + n];
        else if (n < 64) v = W1l_rev[k * HH + n - 32];
        else             v = W1r_c[k * HH + n - 64] + W1r_w[k * HH + n - 64];
        __nv_bfloat16 h = __float2bfloat16(v);
        g_WbP[q] = lo ? __float2bfloat16(v - __bfloat162float(h)) : h;
    }
    for (int q = idx; q < 64 * 128; q += stride) {
        int n = q >> 7, kc = q & 127;
        int k = kc & 63;
        bool lo = kc >= 64;
        float v = (n < 32) ? W1l_w[k * HH + n] : W1r_rev[k * HH + n - 32];
        __nv_bfloat16 h = __float2bfloat16(v);
        g_WbA[q] = lo ? __float2bfloat16(v - __bfloat162float(h)) : h;
    }
    if (idx < HH) {
        g_b1[idx]   = b1l_c[idx] + b1l_w[idx];
        g_brev[idx] = b1l_rev[idx];
        float uc = 0.f, uw = 0.f, wr = 0.f;
        for (int j = 0; j < HH; ++j) {
            float wh = Wh[j];
            uc += W2l_c[idx * HH + j] * wh;
            uw += W2l_w[idx * HH + j] * wh;
            wr += (W2r_c[idx * HH + j] + W2r_w[idx * HH + j]) * wh;
        }
        g_uc[idx] = uc; g_uw[idx] = uw; g_wr2[idx] = wr;
    }
    if (idx == 0) {
        float cb = bh[0];
        for (int j = 0; j < HH; ++j) cb += (b2l_c[j] + b2l_w[j]) * Wh[j];
        g_cbias = cb;
    }
}

// ---------------- CSR build (side stream); 4 edges/thread (MLP=4) ----------------
// Relation blocks are 1M edges (4-aligned), so a thread's 4 edges share one relation.
__global__ void k_hist3(const int* __restrict__ dc, const int* __restrict__ dw,
                        const int* __restrict__ dr) {
    int t = blockIdx.x * blockDim.x + threadIdx.x;
    int e = t * 4;
    if (e >= 3 * EE) return;
    const int* d; int off, le;
    if (e < EE)          { d = dc; off = 0;      le = e; }
    else if (e < 2 * EE) { d = dw; off = NP;     le = e - EE; }
    else                 { d = dr; off = 2 * NP; le = e - 2 * EE; }
    int4 dd = __ldg((const int4*)(d + le));
    int4 rk;
    rk.x = atomicAdd(&g_deg[off + dd.x], 1);
    rk.y = atomicAdd(&g_deg[off + dd.y], 1);
    rk.z = atomicAdd(&g_deg[off + dd.z], 1);
    rk.w = atomicAdd(&g_deg[off + dd.w], 1);
    *(int4*)(g_rank + e) = rk;
}

__global__ void k_alloc3() {
    __shared__ int sm[256];
    __shared__ int sbase;
    int b = blockIdx.x;
    int off, n, cidx, lb;
    if (b < 196)      { off = 0;      n = NP; cidx = 0; lb = b; }
    else if (b < 392) { off = NP;     n = NP; cidx = 1; lb = b - 196; }
    else              { off = 2 * NP; n = NA; cidx = 2; lb = b - 392; }

    int t = threadIdx.x;
    int idx0 = lb * 1024 + t * 4;
    int d0 = (idx0 + 0 < n) ? g_deg[off + idx0 + 0] : 0;
    int d1 = (idx0 + 1 < n) ? g_deg[off + idx0 + 1] : 0;
    int d2 = (idx0 + 2 < n) ? g_deg[off + idx0 + 2] : 0;
    int d3 = (idx0 + 3 < n) ? g_deg[off + idx0 + 3] : 0;
    int s = d0 + d1 + d2 + d3;
    sm[t] = s;
    __syncthreads();
    for (int o = 1; o < 256; o <<= 1) {
        int v = (t >= o) ? sm[t - o] : 0;
        __syncthreads();
        sm[t] += v;
        __syncthreads();
    }
    if (t == 255) sbase = atomicAdd(&g_cnt[cidx], sm[255]);
    __syncthreads();
    int start = sbase + sm[t] - s;
    if (idx0 + 0 < n) { g_rp[off + idx0 + 0] = start; start += d0; }
    if (idx0 + 1 < n) { g_rp[off + idx0 + 1] = start; start += d1; }
    if (idx0 + 2 < n) { g_rp[off + idx0 + 2] = start; start += d2; }
    if (idx0 + 3 < n) { g_rp[off + idx0 + 3] = start; }
}

// atomic-free fill; 4 edges/thread
__global__ void k_fill3(const int* __restrict__ sc, const int* __restrict__ dc,
                        const int* __restrict__ sw, const int* __restrict__ dw,
                        const int* __restrict__ sr, const int* __restrict__ dr) {
    int t = blockIdx.x * blockDim.x + threadIdx.x;
    int e = t * 4;
    if (e >= 3 * EE) return;
    const int* s; const int* d; int off, colOff, le;
    if (e < EE)          { s = sc; d = dc; off = 0;      colOff = 0;      le = e; }
    else if (e < 2 * EE) { s = sw; d = dw; off = NP;     colOff = EE;     le = e - EE; }
    else                 { s = sr; d = dr; off = 2 * NP; colOff = 2 * EE; le = e - 2 * EE; }
    int4 dd = __ldg((const int4*)(d + le));
    int4 rk = *(const int4*)(g_rank + e);
    int4 ss = __ldg((const int4*)(s + le));
    int p0 = __ldg(&g_rp[off + dd.x]) + rk.x;
    int p1 = __ldg(&g_rp[off + dd.y]) + rk.y;
    int p2 = __ldg(&g_rp[off + dd.z]) + rk.z;
    int p3 = __ldg(&g_rp[off + dd.w]) + rk.w;
    g_col[colOff + p0] = ss.x;
    g_col[colOff + p1] = ss.y;
    g_col[colOff + p2] = ss.z;
    g_col[colOff + p3] = ss.w;
}

// ---------------- bf16 3-term-split GEMM body ----------------
template <int K, int N, int WHICH>
__device__ __forceinline__ void gemm_body(const float* __restrict__ A,
                                          const __nv_bfloat16* __restrict__ B, // [N][2K]
                                          int M, int row0,
                                          __nv_bfloat16* As, __nv_bfloat16* Bs) {
    constexpr int CK  = 32;
    constexpr int NCH = K / CK;
    constexpr int STR = 2 * CK + 8;   // 72
    constexpr int NP2 = N / 32;
    constexpr int NT  = N / 16;

    const int tid = threadIdx.x;
    const int warp = tid >> 5, lane = tid & 31;
    const int wr = warp & 3, wc = warp >> 2;
    const int lr = lane & 7, sel = lane >> 3;
    const uint32_t As_u = smem_u32(As), Bs_u = smem_u32(Bs);

    float d[2][NT][4];
#pragma unroll
    for (int rg = 0; rg < 2; ++rg)
#pragma unroll
        for (int nt = 0; nt < NT; ++nt)
#pragma unroll
            for (int j = 0; j < 4; ++j) d[rg][nt][j] = 0.f;

#pragma unroll
    for (int ch = 0; ch < NCH; ++ch) {
        __syncthreads();
        {
            const int q = tid & 3, r0 = tid >> 2;
#pragma unroll
            for (int i = 0; i < 2; ++i) {
                int r = r0 + 64 * i;
                int gr = row0 + r; if (gr > M - 1) gr = M - 1;
                const float4* p = (const float4*)(A + (size_t)gr * K + ch * CK + q * 8);
                float4 va = p[0], vb = p[1];
                float f[8] = {va.x, va.y, va.z, va.w, vb.x, vb.y, vb.z, vb.w};
                float h[8], l[8];
#pragma unroll
                for (int j = 0; j < 8; ++j) {
                    h[j] = __bfloat162float(__float2bfloat16(f[j]));
                    l[j] = f[j] - h[j];
                }
                uint4 HI = {pack_bf16(h[0], h[1]), pack_bf16(h[2], h[3]),
                            pack_bf16(h[4], h[5]), pack_bf16(h[6], h[7])};
                uint4 LO = {pack_bf16(l[0], l[1]), pack_bf16(l[2], l[3]),
                            pack_bf16(l[4], l[5]), pack_bf16(l[6], l[7])};
                *(uint4*)(As + r * STR + q * 8)      = HI;
                *(uint4*)(As + r * STR + CK + q * 8) = LO;
            }
        }
        for (int u = tid; u < N * 8; u += 256) {
            int n = u >> 3, grp = u & 7;
            int srcCol = (grp < 4) ? (ch * CK + grp * 8) : (K + ch * CK + (grp - 4) * 8);
            *(uint4*)(Bs + n * STR + grp * 8) = *(const uint4*)(B + n * 2 * K + srcCol);
        }
        __syncthreads();

#pragma unroll
        for (int ks = 0; ks < CK / 16; ++ks) {
            const uint32_t a_base = As_u + (uint32_t)(((wr * 32 + lr + (sel & 1) * 8) * STR +
                                                       ks * 16 + (sel >> 1) * 8) * 2);
            const uint32_t b_base = Bs_u + (uint32_t)(((wc * (N / 2) + lr + (sel >> 1) * 8) * STR +
                                                       ks * 16 + (sel & 1) * 8) * 2);
            uint32_t ah[2][4], al[2][4];
#pragma unroll
            for (int rg = 0; rg < 2; ++rg)
                ldsm4(ah[rg][0], ah[rg][1], ah[rg][2], ah[rg][3],
                      a_base + (uint32_t)(rg * 16 * STR * 2));
#pragma unroll
            for (int rg = 0; rg < 2; ++rg)
                ldsm4(al[rg][0], al[rg][1], al[rg][2], al[rg][3],
                      a_base + (uint32_t)((rg * 16 * STR + CK) * 2));
#pragma unroll
            for (int np = 0; np < NP2; ++np) {
                uint32_t b0, b1, b2, b3;
                ldsm4(b0, b1, b2, b3, b_base + (uint32_t)(np * 16 * STR * 2));
#pragma unroll
                for (int rg = 0; rg < 2; ++rg) {
                    mma16816(d[rg][2 * np],     ah[rg], b0, b1);
                    mma16816(d[rg][2 * np + 1], ah[rg], b2, b3);
                }
#pragma unroll
                for (int rg = 0; rg < 2; ++rg) {
                    mma16816(d[rg][2 * np],     al[rg], b0, b1);
                    mma16816(d[rg][2 * np + 1], al[rg], b2, b3);
                }
                ldsm4(b0, b1, b2, b3, b_base + (uint32_t)((np * 16 * STR + CK) * 2));
#pragma unroll
                for (int rg = 0; rg < 2; ++rg) {
                    mma16816(d[rg][2 * np],     ah[rg], b0, b1);
                    mma16816(d[rg][2 * np + 1], ah[rg], b2, b3);
                }
            }
        }
    }

    const int g = lane >> 2, t = lane & 3;
#pragma unroll
    for (int rg = 0; rg < 2; ++rg) {
        const int r1 = row0 + wr * 32 + rg * 16 + g, r2 = r1 + 8;
#pragma unroll
        for (int nt = 0; nt < NT; ++nt) {
            int col = wc * (N / 2) + nt * 8 + 2 * t;
            int pl = col >> 5, cc = col & 31;
            bool fp16plane; __half* H; float* F;
            if (WHICH == 0) {
                fp16plane = (pl < 2);
                H = (pl == 0) ? g_P0 : g_P1;
                F = g_P2;
            } else {
                fp16plane = (pl == 0);
                H = g_A0;
                F = g_A1;
            }
            if (fp16plane) {
                __half2 v1 = __floats2half2_rn(d[rg][nt][0], d[rg][nt][1]);
                __half2 v2 = __floats2half2_rn(d[rg][nt][2], d[rg][nt][3]);
                if (r1 < M) *(__half2*)(H + (size_t)r1 * 32 + cc) = v1;
                if (r2 < M) *(__half2*)(H + (size_t)r2 * 32 + cc) = v2;
            } else {
                if (r1 < M) *(float2*)(F + (size_t)r1 * 32 + cc) = make_float2(d[rg][nt][0], d[rg][nt][1]);
                if (r2 < M) *(float2*)(F + (size_t)r2 * 32 + cc) = make_float2(d[rg][nt][2], d[rg][nt][3]);
            }
        }
    }
}

__global__ void __launch_bounds__(256, 3) k_gemm_all(const float* __restrict__ xp,
                                                     const float* __restrict__ xa) {
    __shared__ __nv_bfloat16 sm[128 * 72 + 96 * 72];
    if (blockIdx.x < GEMM_BLKS_P)
        gemm_body<128, 96, 0>(xp, g_WbP, NP, blockIdx.x * 128, sm, sm + 128 * 72);
    else
        gemm_body<64, 64, 1>(xa, g_WbA, NA, (blockIdx.x - GEMM_BLKS_P) * 128, sm, sm + 128 * 72);
}

// ---------------- k_pa: fused dual gather (2x MLP on the latency chain) ----------------
__global__ void __launch_bounds__(256) k_pa() {
    int lane = threadIdx.x & 31;
    int h = lane >> 4, lh = lane & 15;
    if (blockIdx.x < PA_BLKS_P) {
        int w = blockIdx.x * 8 + (threadIdx.x >> 5);
        int s  = __ldg(&g_rp[w]);      int d  = __ldg(&g_deg[w]);
        int s2 = __ldg(&g_rp[NP + w]); int d2 = __ldg(&g_deg[NP + w]);
        const int* colA = g_col + s;
        const int* colB = g_col + EE + s2;
        const __half2* baseA = (const __half2*)g_P0;
        const __half2* baseB = (const __half2*)g_A0;

        float ax = 0.f, ay = 0.f, bx = 0.f, by = 0.f;
        int dm = max(d, d2);
        for (int e0 = 0; e0 < dm; e0 += 8) {
            int ia[4], ib[4];
#pragma unroll
            for (int j = 0; j < 4; ++j) {
                int e = e0 + h + 2 * j;
                ia[j] = (e < d)  ? __ldg(colA + e) : -1;
                ib[j] = (e < d2) ? __ldg(colB + e) : -1;
            }
#pragma unroll
            for (int j = 0; j < 4; ++j) {
                if (ia[j] >= 0) {
                    float2 f = __half22float2(__ldg(baseA + (size_t)ia[j] * 16 + lh));
                    ax += f.x; ay += f.y;
                }
                if (ib[j] >= 0) {
                    float2 f = __half22float2(__ldg(baseB + (size_t)ib[j] * 16 + lh));
                    bx += f.x; by += f.y;
                }
            }
        }
        float invA = 1.f / fmaxf((float)d, 1.f);
        float invB = 1.f / fmaxf((float)d2, 1.f);
        float mx = ax * invA + bx * invB;
        float my = ay * invA + by * invB;
        mx += __shfl_xor_sync(0xFFFFFFFFu, mx, 16);
        my += __shfl_xor_sync(0xFFFFFFFFu, my, 16);

        float2 self = *(const float2*)(g_P2 + (size_t)w * 32 + 2 * lh);
        float2 b1   = *(const float2*)(g_b1 + 2 * lh);
        float px = fmaxf(mx + self.x + b1.x, 0.f);
        float py = fmaxf(my + self.y + b1.y, 0.f);

        float2 uc2 = *(const float2*)(g_uc + 2 * lh);
        float2 wr2 = *(const float2*)(g_wr2 + 2 * lh);
        float zc = px * uc2.x + py * uc2.y;
        float zr = px * wr2.x + py * wr2.y;
#pragma unroll
        for (int o = 16; o; o >>= 1) {
            zc += __shfl_xor_sync(0xFFFFFFFFu, zc, o);
            zr += __shfl_xor_sync(0xFFFFFFFFu, zr, o);
        }
        if (lane == 0) { g_zc[w] = 0.5f * zc; g_zr[w] = 0.5f * zr; }
    } else {
        int w = (blockIdx.x - PA_BLKS_P) * 8 + (threadIdx.x >> 5);
        int s = __ldg(&g_rp[2 * NP + w]); int d = __ldg(&g_deg[2 * NP + w]);
        const int* col = g_col + 2 * EE + s;
        const __half2* base = (const __half2*)g_P1;

        float sx = 0.f, sy = 0.f;
        for (int e0 = 0; e0 < d; e0 += 8) {
            int idx[4];
#pragma unroll
            for (int j = 0; j < 4; ++j) {
                int e = e0 + h + 2 * j;
                idx[j] = (e < d) ? __ldg(col + e) : -1;
            }
#pragma unroll
            for (int j = 0; j < 4; ++j) {
                if (idx[j] >= 0) {
                    float2 f = __half22float2(__ldg(base + (size_t)idx[j] * 16 + lh));
                    sx += f.x; sy += f.y;
                }
            }
        }
        float inv = 1.f / fmaxf((float)d, 1.f);
        float mx = sx * inv, my = sy * inv;
        mx += __shfl_xor_sync(0xFFFFFFFFu, mx, 16);
        my += __shfl_xor_sync(0xFFFFFFFFu, my, 16);

        float2 self = *(const float2*)(g_A1 + (size_t)w * 32 + 2 * lh);
        float2 br   = *(const float2*)(g_brev + 2 * lh);
        float px = fmaxf(mx + self.x + br.x, 0.f);
        float py = fmaxf(my + self.y + br.y, 0.f);

        float2 uw2 = *(const float2*)(g_uw + 2 * lh);
        float zw = px * uw2.x + py * uw2.y;
#pragma unroll
        for (int o = 16; o; o >>= 1) zw += __shfl_xor_sync(0xFFFFFFFFu, zw, o);
        if (lane == 0) g_zw[w] = 0.5f * zw;
    }
}

// ---------------- k_out: fused dual scalar gather; restores g_deg/g_cnt ----------------
__global__ void __launch_bounds__(256) k_out(float* __restrict__ out) {
    int i = blockIdx.x * blockDim.x + threadIdx.x;
    if (i >= NP) return;
    int s  = __ldg(&g_rp[i]);      int d  = __ldg(&g_deg[i]);
    int s2 = __ldg(&g_rp[NP + i]); int d2 = __ldg(&g_deg[NP + i]);
    const int* colA = g_col + s;
    const int* colB = g_col + EE + s2;

    float sa = 0.f, sb = 0.f;
    int dm = max(d, d2);
    for (int e = 0; e < dm; e += 8) {
        int ia[8], ib[8];
#pragma unroll
        for (int j = 0; j < 8; ++j) {
            ia[j] = (e + j < d)  ? __ldg(colA + e + j) : -1;
            ib[j] = (e + j < d2) ? __ldg(colB + e + j) : -1;
        }
        float va = 0.f, vb = 0.f;
#pragma unroll
        for (int j = 0; j < 8; ++j) {
            if (ia[j] >= 0) va += __ldg(g_zc + ia[j]);
            if (ib[j] >= 0) vb += __ldg(g_zw + ib[j]);
        }
        sa += va; sb += vb;
    }
    out[i] = sa / fmaxf((float)d, 1.f) + sb / fmaxf((float)d2, 1.f) + __ldg(&g_zr[i]) + g_cbias;
    // state restore for next graph replay
    g_deg[i] = 0;
    g_deg[NP + i] = 0;
    if (i < NA) g_deg[2 * NP + i] = 0;
    if (i < 3) g_cnt[i] = 0;
}

// ---------------- launch: fork/join ----------------
extern "C" void kernel_launch(void* const* d_in, const int* in_sizes, int n_in,
                              void* d_out, int out_size) {
    const float* x_paper  = (const float*)d_in[0];
    const float* x_author = (const float*)d_in[1];
    const int*   ei_c     = (const int*)d_in[2];
    const int*   ei_w     = (const int*)d_in[3];
    const int*   ei_r     = (const int*)d_in[4];
    float* out = (float*)d_out;

    static cudaStream_t s_side = nullptr;
    static cudaEvent_t s_evF = nullptr, s_evJ = nullptr;
    if (s_side == nullptr) {
        cudaStreamCreateWithFlags(&s_side, cudaStreamNonBlocking);
        cudaEventCreateWithFlags(&s_evF, cudaEventDisableTiming);
        cudaEventCreateWithFlags(&s_evJ, cudaEventDisableTiming);
    }

    cudaEventRecord(s_evF, 0);
    cudaStreamWaitEvent(s_side, s_evF, 0);

    // side branch: CSR build (4 edges/thread)
    k_hist3<<<H4_BLKS, 256, 0, s_side>>>(ei_c + EE, ei_w + EE, ei_r + EE);
    k_alloc3<<<490, 256, 0, s_side>>>();
    k_fill3<<<H4_BLKS, 256, 0, s_side>>>(ei_c, ei_c + EE, ei_w, ei_w + EE, ei_r, ei_r + EE);
    cudaEventRecord(s_evJ, s_side);

    // main branch: weight prep + projection GEMM
    k_prep<<<48, 256>>>(
        (const float*)d_in[5],  (const float*)d_in[6],  (const float*)d_in[7],
        (const float*)d_in[8],  (const float*)d_in[9],  (const float*)d_in[10],
        (const float*)d_in[11], (const float*)d_in[12], (const float*)d_in[13],
        (const float*)d_in[14], (const float*)d_in[15], (const float*)d_in[16],
        (const float*)d_in[17], (const float*)d_in[18], (const float*)d_in[19],
        (const float*)d_in[23], (const float*)d_in[24]);
    k_gemm_all<<<GEMM_BLKS, 256>>>(x_paper, x_author);

    cudaStreamWaitEvent(0, s_evJ, 0);
    k_pa<<<PA_BLKS_P + PA_BLKS_A, 256>>>();
    k_out<<<(NP + 255) / 256, 256>>>(out);
}